// round 10
// baseline (speedup 1.0000x reference)
#include <cuda_runtime.h>
#include <cuda_fp16.h>
#include <cstdint>

// Problem constants
#define BB 16
#define SS 2048
#define DD 1024
#define HH 16
#define DK 64
#define CLIPC 8
#define NCC 256
#define MROWS (BB * SS)  // 32768

// ---------------------------------------------------------------------------
// Scratch (static __device__ arrays; no allocation allowed)
// ---------------------------------------------------------------------------
__device__ float g_W1[DD * DD];
__device__ float g_W2[DD * DD];
__device__ float g_bc[DD];
__device__ float g_bcp[32][DD];

// fp16 buffers
__device__ __half g_qs[MROWS * DD];   // q/k/v now fp16 (GEMM writes directly)
__device__ __half g_ks[MROWS * DD];
__device__ __half g_vs[MROWS * DD];
__device__ __half g_qt[MROWS * DD];
__device__ __half g_kt[MROWS * DD];
__device__ __half g_vt[MROWS * DD];
__device__ __half g_xh[MROWS * DD];
__device__ __half g_csh[MROWS * DD];   // spatial attention out
__device__ __half g_cth[MROWS * DD];   // temporal attention out
// transposed+split weights: 0..5 = sa_q,sa_k,sa_v,ta_q,ta_k,ta_v; 6=W1; 7=W2
__device__ __half g_wth[8][DD * DD];
__device__ __half g_wtl[8][DD * DD];

// ---------------------------------------------------------------------------
// Packed f32x2 helpers
// ---------------------------------------------------------------------------
__device__ __forceinline__ unsigned long long pk2(float lo, float hi) {
    unsigned long long r;
    asm("mov.b64 %0, {%1, %2};" : "=l"(r) : "f"(lo), "f"(hi));
    return r;
}
__device__ __forceinline__ void fma2(unsigned long long& d, unsigned long long a,
                                     unsigned long long b) {
    asm("fma.rn.f32x2 %0, %1, %2, %0;" : "+l"(d) : "l"(a), "l"(b));
}
__device__ __forceinline__ void mul2(unsigned long long& d, unsigned long long a) {
    asm("mul.rn.f32x2 %0, %0, %1;" : "+l"(d) : "l"(a));
}
__device__ __forceinline__ float2 upk(unsigned long long v) {
    float2 f;
    asm("mov.b64 {%0, %1}, %2;" : "=f"(f.x), "=f"(f.y) : "l"(v));
    return f;
}
// half2 (as u32) -> packed f32x2
__device__ __forceinline__ unsigned long long h2tof2(uint32_t h) {
    float2 f = __half22float2(*(__half2*)&h);
    return pk2(f.x, f.y);
}

// ---------------------------------------------------------------------------
// mma.sync helpers (base PTX ISA — compiles at .target sm_103)
// ---------------------------------------------------------------------------
__device__ __forceinline__ uint32_t smem_u32(const void* p) {
    uint32_t a;
    asm("{ .reg .u64 t; cvta.to.shared.u64 t, %1; cvt.u32.u64 %0, t; }"
        : "=r"(a) : "l"(p));
    return a;
}
__device__ __forceinline__ void ldsm4(uint32_t* r, uint32_t addr) {
    asm volatile(
        "ldmatrix.sync.aligned.m8n8.x4.shared.b16 {%0,%1,%2,%3}, [%4];"
        : "=r"(r[0]), "=r"(r[1]), "=r"(r[2]), "=r"(r[3]) : "r"(addr));
}
__device__ __forceinline__ void mma16816(float* d, const uint32_t* a,
                                         const uint32_t* b) {
    asm volatile(
        "mma.sync.aligned.m16n8k16.row.col.f32.f16.f16.f32 "
        "{%0,%1,%2,%3}, {%4,%5,%6,%7}, {%8,%9}, {%0,%1,%2,%3};"
        : "+f"(d[0]), "+f"(d[1]), "+f"(d[2]), "+f"(d[3])
        : "r"(a[0]), "r"(a[1]), "r"(a[2]), "r"(a[3]), "r"(b[0]), "r"(b[1]));
}
#define CPASYNC16(dst, src) \
    asm volatile("cp.async.cg.shared.global [%0], [%1], 16;" :: "r"(dst), "l"(src))
#define CPCOMMIT() asm volatile("cp.async.commit_group;" ::: "memory")
#define CPWAIT2() asm volatile("cp.async.wait_group 2;" ::: "memory")

// smem geometry: row pitch 80B (40 fp16), conflict-free for ldmatrix.
#define PITCHB 80
#define TILEB (128 * PITCHB)     // 10240 bytes per operand tile
#define STAGEB (3 * TILEB)       // Ah, Bh, Bl
#define NSTAGE 3
#define SMEM_DYN (NSTAGE * STAGEB)  // 92160 bytes

// ---------------------------------------------------------------------------
// fp16 2-pass GEMM core: C = Ah*Bh^T + Ah*Bl^T + bias; output fp32 OR fp16.
// CTA tile 128x128, BK=32, 8 warps (4M x 2N), 3-stage cp.async. (R4 config)
// ---------------------------------------------------------------------------
struct GSrc {
    const __half *Ah, *Bh, *Bl;
};

__device__ __forceinline__ void mma_core(
    GSrc s0, GSrc s1, int nchunk,
    const float* __restrict__ bias, float* __restrict__ C,
    __half* __restrict__ C16, int bm, int bn)
{
    extern __shared__ char sm[];
    const uint32_t sbase = smem_u32(sm);
    const int tid = threadIdx.x, wid = tid >> 5, l = tid & 31;
    const int wm = (wid & 3) * 32;   // warp row offset in CTA tile
    const int wn = (wid >> 2) * 64;  // warp col offset

    auto issue = [&](int kc) {
        if (kc < nchunk) {
            const GSrc& s = (kc < 32) ? s0 : s1;
            const int kl = kc & 31;
            const uint32_t st = sbase + (kc % NSTAGE) * STAGEB;
            const __half* srcs[3] = {s.Ah, s.Bh, s.Bl};
#pragma unroll
            for (int t3 = 0; t3 < 3; ++t3) {
                const int rb = (t3 == 0) ? bm : bn;
                const uint32_t doff = st + t3 * TILEB;
                const __half* sp = srcs[t3];
#pragma unroll
                for (int j = 0; j < 2; ++j) {
                    int c = tid + j * 256;
                    int row = c >> 2, pos = c & 3;
                    uint32_t dst = doff + row * PITCHB + pos * 16;
                    const void* src = sp + (size_t)(rb + row) * DD + kl * 32 + pos * 8;
                    CPASYNC16(dst, src);
                }
            }
        }
        CPCOMMIT();
    };

    issue(0);
    issue(1);
    issue(2);

    float acc[2][8][4];
#pragma unroll
    for (int mi = 0; mi < 2; ++mi)
#pragma unroll
        for (int ni = 0; ni < 8; ++ni)
#pragma unroll
            for (int f = 0; f < 4; ++f) acc[mi][ni][f] = 0.0f;

    const uint32_t m8 = l >> 3;
    const uint32_t laneArow = (m8 & 1) * 8 + (l & 7);
    const uint32_t laneAkb = (m8 >> 1) * 16;
    const uint32_t laneBrow = (m8 >> 1) * 8 + (l & 7);
    const uint32_t laneBkb = (m8 & 1) * 16;

    for (int kc = 0; kc < nchunk; ++kc) {
        CPWAIT2();
        __syncthreads();
        const uint32_t st = sbase + (kc % NSTAGE) * STAGEB;
#pragma unroll
        for (int ks = 0; ks < 2; ++ks) {
            const uint32_t kbyte = ks * 32;
            uint32_t ah[2][4];
#pragma unroll
            for (int mi = 0; mi < 2; ++mi) {
                uint32_t r = wm + mi * 16 + laneArow;
                ldsm4(ah[mi], st + 0 * TILEB + r * PITCHB + kbyte + laneAkb);
            }
            uint32_t bh[8][2], bl[8][2];
#pragma unroll
            for (int bi = 0; bi < 4; ++bi) {
                uint32_t r = wn + bi * 16 + laneBrow;
                uint32_t q[4];
                ldsm4(q, st + 1 * TILEB + r * PITCHB + kbyte + laneBkb);
                bh[bi * 2][0] = q[0]; bh[bi * 2][1] = q[1];
                bh[bi * 2 + 1][0] = q[2]; bh[bi * 2 + 1][1] = q[3];
                ldsm4(q, st + 2 * TILEB + r * PITCHB + kbyte + laneBkb);
                bl[bi * 2][0] = q[0]; bl[bi * 2][1] = q[1];
                bl[bi * 2 + 1][0] = q[2]; bl[bi * 2 + 1][1] = q[3];
            }
#pragma unroll
            for (int mi = 0; mi < 2; ++mi)
#pragma unroll
                for (int ni = 0; ni < 8; ++ni) {
                    mma16816(acc[mi][ni], ah[mi], bh[ni]);
                    mma16816(acc[mi][ni], ah[mi], bl[ni]);
                }
        }
        __syncthreads();
        issue(kc + NSTAGE);
    }

    // epilogue
#pragma unroll
    for (int mi = 0; mi < 2; ++mi) {
        const int r0 = bm + wm + mi * 16 + (l >> 2);
#pragma unroll
        for (int ni = 0; ni < 8; ++ni) {
            const int c = bn + wn + ni * 8 + (l & 3) * 2;
            const float b0v = bias[c], b1v = bias[c + 1];
            float o00 = acc[mi][ni][0] + b0v, o01 = acc[mi][ni][1] + b1v;
            float o10 = acc[mi][ni][2] + b0v, o11 = acc[mi][ni][3] + b1v;
            if (C16) {
                *(__half2*)(C16 + (size_t)r0 * DD + c) = __floats2half2_rn(o00, o01);
                *(__half2*)(C16 + (size_t)(r0 + 8) * DD + c) = __floats2half2_rn(o10, o11);
            } else {
                *(float2*)(C + (size_t)r0 * DD + c) = make_float2(o00, o01);
                *(float2*)(C + (size_t)(r0 + 8) * DD + c) = make_float2(o10, o11);
            }
        }
    }
}

// batched QKV: z selects weight/bias/output; outputs fp16
struct QkvPtrs {
    const __half* Bh[6];
    const __half* Bl[6];
    const float* bias[6];
    __half* C[6];
};

__global__ __launch_bounds__(256) void mma_gemm_qkv(
    const __half* __restrict__ Ah, QkvPtrs p)
{
    int z = blockIdx.z;
    GSrc s{Ah, p.Bh[z], p.Bl[z]};
    mma_core(s, s, 32, p.bias[z], nullptr, p.C[z],
             blockIdx.y * 128, blockIdx.x * 128);
}

__global__ __launch_bounds__(256) void mma_gemm_dual(
    const __half* A0h, const __half* B0h, const __half* B0l,
    const __half* A1h, const __half* B1h, const __half* B1l,
    const float* bias, float* C)
{
    GSrc s0{A0h, B0h, B0l};
    GSrc s1{A1h, B1h, B1l};
    mma_core(s0, s1, 64, bias, C, nullptr, blockIdx.y * 128, blockIdx.x * 128);
}

// ---------------------------------------------------------------------------
// fp32 -> fp16 convert (hi only), vectorized
// ---------------------------------------------------------------------------
__global__ __launch_bounds__(256) void cvt_half(
    const float4* __restrict__ X, __half* __restrict__ H)
{
    size_t idx = (size_t)blockIdx.x * 256 + threadIdx.x;
    float4 v = X[idx];
    __half h[4];
    h[0] = __float2half(v.x);
    h[1] = __float2half(v.y);
    h[2] = __float2half(v.z);
    h[3] = __float2half(v.w);
    *(uint2*)(H + idx * 4) = *(uint2*)h;
}

// ---------------------------------------------------------------------------
// Weight transpose + split (z-batched): W[K=1024, N=1024] fp32 -> Th/Tl [N,K]
// ---------------------------------------------------------------------------
struct WtPtrs {
    const float* W[6];
    __half* Th[6];
    __half* Tl[6];
    int n;
};

__device__ __forceinline__ void wt_split_body(
    const float* __restrict__ W, __half* __restrict__ Th,
    __half* __restrict__ Tl)
{
    __shared__ float t[32][33];
    int tx = threadIdx.x, ty = threadIdx.y;
    int n0 = blockIdx.x * 32, k0 = blockIdx.y * 32;
#pragma unroll
    for (int j = 0; j < 4; ++j) {
        int k = k0 + ty + j * 8;
        t[ty + j * 8][tx] = W[(size_t)k * DD + n0 + tx];
    }
    __syncthreads();
#pragma unroll
    for (int j = 0; j < 4; ++j) {
        int n = n0 + ty + j * 8;
        int k = k0 + tx;
        float v = t[tx][ty + j * 8];
        __half h = __float2half(v);
        __half lo = __float2half(v - __half2float(h));
        Th[(size_t)n * DD + k] = h;
        Tl[(size_t)n * DD + k] = lo;
    }
}

__global__ void wt_split_batch(WtPtrs p)
{
    int z = blockIdx.z;
    wt_split_body(p.W[z], p.Th[z], p.Tl[z]);
}

// ---------------------------------------------------------------------------
// Scalar fp32 GEMM body (fixed 1024x1024x1024, no bias) + z=2 fold kernel
// ---------------------------------------------------------------------------
__device__ __forceinline__ void gemm_scalar_body(
    const float* __restrict__ A, const float* __restrict__ B,
    float* __restrict__ C)
{
    __shared__ float As[16][128];
    __shared__ float Bs[16][128];
    const int tid = threadIdx.x;
    const int bm = blockIdx.y * 128;
    const int bn = blockIdx.x * 128;
    const int tm = (tid >> 4) << 3;
    const int tn = (tid & 15) << 3;

    unsigned long long acc2[8][4];
#pragma unroll
    for (int i = 0; i < 8; ++i)
#pragma unroll
        for (int j = 0; j < 4; ++j) acc2[i][j] = 0ull;

    const int nk = DD >> 4;
    float4 aR[2], bR[2];
    auto loadTile = [&](int kt) {
        const int k0 = kt << 4;
#pragma unroll
        for (int j = 0; j < 2; ++j) {
            int i = tid + (j << 8);
            int ar = i >> 2, ac = (i & 3) << 2;
            aR[j] = *(const float4*)(A + (size_t)(bm + ar) * DD + k0 + ac);
            int br = i >> 5, bc = (i & 31) << 2;
            bR[j] = *(const float4*)(B + (size_t)(k0 + br) * DD + bn + bc);
        }
    };
    auto storeTile = [&]() {
#pragma unroll
        for (int j = 0; j < 2; ++j) {
            int i = tid + (j << 8);
            int ar = i >> 2, ac = (i & 3) << 2;
            As[ac + 0][ar] = aR[j].x;
            As[ac + 1][ar] = aR[j].y;
            As[ac + 2][ar] = aR[j].z;
            As[ac + 3][ar] = aR[j].w;
            int br = i >> 5, bc = (i & 31) << 2;
            *(float4*)&Bs[br][bc] = bR[j];
        }
    };
    loadTile(0);
    storeTile();
    __syncthreads();
    for (int kt = 0; kt < nk; ++kt) {
        if (kt + 1 < nk) loadTile(kt + 1);
#pragma unroll
        for (int k = 0; k < 16; ++k) {
            float4 a0 = *(const float4*)&As[k][tm];
            float4 a1 = *(const float4*)&As[k][tm + 4];
            float4 b0 = *(const float4*)&Bs[k][tn];
            float4 b1 = *(const float4*)&Bs[k][tn + 4];
            unsigned long long rbp[4] = {pk2(b0.x, b0.y), pk2(b0.z, b0.w),
                                         pk2(b1.x, b1.y), pk2(b1.z, b1.w)};
            float ra[8] = {a0.x, a0.y, a0.z, a0.w, a1.x, a1.y, a1.z, a1.w};
#pragma unroll
            for (int i = 0; i < 8; ++i) {
                unsigned long long aa = pk2(ra[i], ra[i]);
#pragma unroll
                for (int jp = 0; jp < 4; ++jp) fma2(acc2[i][jp], aa, rbp[jp]);
            }
        }
        __syncthreads();
        if (kt + 1 < nk) {
            storeTile();
            __syncthreads();
        }
    }
#pragma unroll
    for (int i = 0; i < 8; ++i) {
        float* crow = C + (size_t)(bm + tm + i) * DD + bn + tn;
#pragma unroll
        for (int jp = 0; jp < 4; ++jp) {
            float2 f = upk(acc2[i][jp]);
            *(float2*)(crow + 2 * jp) = f;
        }
    }
}

__global__ __launch_bounds__(256) void fold2_kernel(
    const float* __restrict__ sa_o_w, const float* __restrict__ ta_o_w,
    const float* __restrict__ fuse_w, float* __restrict__ W1,
    float* __restrict__ W2)
{
    if (blockIdx.z == 0)
        gemm_scalar_body(sa_o_w, fuse_w, W1);
    else
        gemm_scalar_body(ta_o_w, fuse_w + (size_t)DD * DD, W2);
}

// ---------------------------------------------------------------------------
// Merged attention (fp16 q/k/v in, fp16 out; fp32 compute).
// Blocks [0,2048) temporal, [2048,4096) spatial.
// ---------------------------------------------------------------------------
__device__ __forceinline__ void temporal_body(
    const __half* __restrict__ Q, const __half* __restrict__ Kp,
    const __half* __restrict__ Vp, const int* __restrict__ mask,
    __half* __restrict__ O, int gid)
{
    __shared__ float Ks[64][64];
    __shared__ float Vs[64][64];
    __shared__ int Msk[64];

    int h = gid & 15;
    int clip = (gid >> 4) & 7;
    int b = gid >> 7;
    const size_t base = ((size_t)b * SS + clip) * DD + h * DK;
    const int RS = CLIPC * DD;

    int cq = threadIdx.x;
    unsigned long long qv[32];
    {
        const uint4* qp = (const uint4*)(Q + base + (size_t)cq * RS);
#pragma unroll
        for (int i = 0; i < 8; ++i) {
            uint4 r = qp[i];
            const uint32_t* pr = (const uint32_t*)&r;
#pragma unroll
            for (int j = 0; j < 4; ++j) qv[i * 4 + j] = h2tof2(pr[j]);
        }
    }
    unsigned long long acc[32];
#pragma unroll
    for (int i = 0; i < 32; ++i) acc[i] = 0ull;
    float mmax = -1e30f, l = 0.f;

    const int lr = threadIdx.x >> 2;
    const int lc = (threadIdx.x & 3) << 4;  // 16 halves per thread

    for (int kt = 0; kt < 4; ++kt) {
        __syncthreads();
        {
            const __half* krow = Kp + base + (size_t)(kt * 64 + lr) * RS;
            const __half* vrow = Vp + base + (size_t)(kt * 64 + lr) * RS;
#pragma unroll
            for (int half8 = 0; half8 < 2; ++half8) {
                uint4 rk = *(const uint4*)(krow + lc + half8 * 8);
                uint4 rv = *(const uint4*)(vrow + lc + half8 * 8);
                const uint32_t* pk = (const uint32_t*)&rk;
                const uint32_t* pv = (const uint32_t*)&rv;
                float* dk = &Ks[lr][lc + half8 * 8];
                float* dv = &Vs[lr][lc + half8 * 8];
#pragma unroll
                for (int j = 0; j < 4; ++j) {
                    float2 fk = __half22float2(*(__half2*)&pk[j]);
                    float2 fv = __half22float2(*(__half2*)&pv[j]);
                    dk[2 * j] = fk.x; dk[2 * j + 1] = fk.y;
                    dv[2 * j] = fv.x; dv[2 * j + 1] = fv.y;
                }
            }
            if (threadIdx.x < 64)
                Msk[threadIdx.x] =
                    mask[(size_t)b * SS + (size_t)(kt * 64 + threadIdx.x) * CLIPC + clip];
        }
        __syncthreads();

        for (int kk = 0; kk < 64; ++kk) {
            if (Msk[kk] == 0) continue;
            const unsigned long long* kr = (const unsigned long long*)&Ks[kk][0];
            unsigned long long d2 = 0ull;
#pragma unroll
            for (int i = 0; i < 32; ++i) fma2(d2, qv[i], kr[i]);
            float2 dd = upk(d2);
            float s = (dd.x + dd.y) * 0.125f;
            if (s > mmax) {
                float corr = __expf(mmax - s);
                unsigned long long cc = pk2(corr, corr);
#pragma unroll
                for (int i = 0; i < 32; ++i) mul2(acc[i], cc);
                l *= corr;
                mmax = s;
            }
            float p = __expf(s - mmax);
            l += p;
            unsigned long long pp = pk2(p, p);
            const unsigned long long* vr = (const unsigned long long*)&Vs[kk][0];
#pragma unroll
            for (int i = 0; i < 32; ++i) fma2(acc[i], pp, vr[i]);
        }
    }
    float inv = 1.0f / l;
    __half2* op = (__half2*)(O + base + (size_t)cq * RS);
#pragma unroll
    for (int i = 0; i < 32; ++i) {
        float2 f = upk(acc[i]);
        op[i] = __floats2half2_rn(f.x * inv, f.y * inv);
    }
}

__device__ __forceinline__ void spatial_body(
    const __half* __restrict__ Q, const __half* __restrict__ Kp,
    const __half* __restrict__ Vp, const int* __restrict__ mask,
    __half* __restrict__ O, int blk)
{
    int unit = blk * 2 + (threadIdx.x >> 7);
    int t = threadIdx.x & 127;
    int h = t >> 3, qi = t & 7;
    int b = unit >> 8, nc = unit & 255;
    size_t rowBase = (size_t)b * SS + (size_t)nc * CLIPC;

    unsigned long long qv[32];
    {
        const uint4* qp = (const uint4*)(Q + (rowBase + qi) * DD + h * DK);
#pragma unroll
        for (int i = 0; i < 8; ++i) {
            uint4 r = qp[i];
            const uint32_t* pr = (const uint32_t*)&r;
#pragma unroll
            for (int j = 0; j < 4; ++j) qv[i * 4 + j] = h2tof2(pr[j]);
        }
    }
    const __half* kbase = Kp + rowBase * DD + h * DK;
    float sc[8];
    float mx = -1e30f;
#pragma unroll
    for (int kk = 0; kk < 8; ++kk) {
        const uint4* kr = (const uint4*)(kbase + (size_t)kk * DD);
        unsigned long long d2 = 0ull;
#pragma unroll
        for (int i = 0; i < 8; ++i) {
            uint4 r = kr[i];
            const uint32_t* pr = (const uint32_t*)&r;
#pragma unroll
            for (int j = 0; j < 4; ++j) fma2(d2, qv[i * 4 + j], h2tof2(pr[j]));
        }
        float2 dd = upk(d2);
        float s = (dd.x + dd.y) * 0.125f;
        sc[kk] = (mask[rowBase + kk] != 0) ? s : -1e30f;
        mx = fmaxf(mx, sc[kk]);
    }
    float p[8], sum = 0.f;
#pragma unroll
    for (int kk = 0; kk < 8; ++kk) {
        p[kk] = __expf(sc[kk] - mx);
        sum += p[kk];
    }
    float inv = 1.0f / sum;
    unsigned long long acc[32];
#pragma unroll
    for (int i = 0; i < 32; ++i) acc[i] = 0ull;
    const __half* vbase = Vp + rowBase * DD + h * DK;
#pragma unroll
    for (int kk = 0; kk < 8; ++kk) {
        unsigned long long pp = pk2(p[kk], p[kk]);
        const uint4* vr = (const uint4*)(vbase + (size_t)kk * DD);
#pragma unroll
        for (int i = 0; i < 8; ++i) {
            uint4 r = vr[i];
            const uint32_t* pr = (const uint32_t*)&r;
#pragma unroll
            for (int j = 0; j < 4; ++j) fma2(acc[i * 4 + j], pp, h2tof2(pr[j]));
        }
    }
    __half2* op = (__half2*)(O + (rowBase + qi) * DD + h * DK);
#pragma unroll
    for (int i = 0; i < 32; ++i) {
        float2 f = upk(acc[i]);
        op[i] = __floats2half2_rn(f.x * inv, f.y * inv);
    }
}

__global__ __launch_bounds__(256) void attn_merged(
    const __half* __restrict__ qs, const __half* __restrict__ ks,
    const __half* __restrict__ vs, const __half* __restrict__ qt,
    const __half* __restrict__ kt, const __half* __restrict__ vt,
    const int* __restrict__ mask, __half* __restrict__ csh,
    __half* __restrict__ cth)
{
    int blk = blockIdx.x;
    if (blk < BB * CLIPC * HH) {
        temporal_body(qt, kt, vt, mask, cth, blk);  // long blocks first
    } else {
        spatial_body(qs, ks, vs, mask, csh, blk - BB * CLIPC * HH);
    }
}

// ---------------------------------------------------------------------------
// bias combine, parallel 2-stage
// ---------------------------------------------------------------------------
__global__ void bias_partial(const float* __restrict__ sab,
                             const float* __restrict__ tab,
                             const float* __restrict__ fw,
                             float* __restrict__ part)
{
    int n = blockIdx.x * 256 + threadIdx.x;
    int j = blockIdx.y;
    int k0 = j * 64;
    float s = 0.f;
#pragma unroll 8
    for (int k = k0; k < k0 + 64; ++k) {
        float coef = (k < DD) ? sab[k] : tab[k - DD];
        s += coef * fw[(size_t)k * DD + n];
    }
    part[(size_t)j * DD + n] = s;
}

__global__ void bias_reduce(const float* __restrict__ part,
                            const float* __restrict__ fb,
                            float* __restrict__ bc)
{
    int n = blockIdx.x * 256 + threadIdx.x;
    float s = fb[n];
#pragma unroll
    for (int j = 0; j < 32; ++j) s += part[(size_t)j * DD + n];
    bc[n] = s;
}

// ---------------------------------------------------------------------------
// Launch sequence
// ---------------------------------------------------------------------------
extern "C" void kernel_launch(void* const* d_in, const int* in_sizes, int n_in,
                              void* d_out, int out_size)
{
    const float* x       = (const float*)d_in[0];
    const int*   mask    = (const int*)d_in[1];
    const float* sa_q_w  = (const float*)d_in[2];
    const float* sa_q_b  = (const float*)d_in[3];
    const float* sa_k_w  = (const float*)d_in[4];
    const float* sa_k_b  = (const float*)d_in[5];
    const float* sa_v_w  = (const float*)d_in[6];
    const float* sa_v_b  = (const float*)d_in[7];
    const float* sa_o_w  = (const float*)d_in[8];
    const float* sa_o_b  = (const float*)d_in[9];
    const float* ta_q_w  = (const float*)d_in[10];
    const float* ta_q_b  = (const float*)d_in[11];
    const float* ta_k_w  = (const float*)d_in[12];
    const float* ta_k_b  = (const float*)d_in[13];
    const float* ta_v_w  = (const float*)d_in[14];
    const float* ta_v_b  = (const float*)d_in[15];
    const float* ta_o_w  = (const float*)d_in[16];
    const float* ta_o_b  = (const float*)d_in[17];
    const float* fuse_w  = (const float*)d_in[18];
    const float* fuse_b  = (const float*)d_in[19];
    float* out = (float*)d_out;

    float *W1, *W2, *bc, *bcp;
    cudaGetSymbolAddress((void**)&W1, g_W1);
    cudaGetSymbolAddress((void**)&W2, g_W2);
    cudaGetSymbolAddress((void**)&bc, g_bc);
    cudaGetSymbolAddress((void**)&bcp, g_bcp);

    __half *qs, *ks, *vs, *qt, *kt, *vt, *xh, *csh, *cth, *wth, *wtl;
    cudaGetSymbolAddress((void**)&qs, g_qs);
    cudaGetSymbolAddress((void**)&ks, g_ks);
    cudaGetSymbolAddress((void**)&vs, g_vs);
    cudaGetSymbolAddress((void**)&qt, g_qt);
    cudaGetSymbolAddress((void**)&kt, g_kt);
    cudaGetSymbolAddress((void**)&vt, g_vt);
    cudaGetSymbolAddress((void**)&xh, g_xh);
    cudaGetSymbolAddress((void**)&csh, g_csh);
    cudaGetSymbolAddress((void**)&cth, g_cth);
    cudaGetSymbolAddress((void**)&wth, g_wth);
    cudaGetSymbolAddress((void**)&wtl, g_wtl);
    const size_t WSZ = (size_t)DD * DD;

    cudaFuncSetAttribute(mma_gemm_qkv, cudaFuncAttributeMaxDynamicSharedMemorySize,
                         SMEM_DYN);
    cudaFuncSetAttribute(mma_gemm_dual, cudaFuncAttributeMaxDynamicSharedMemorySize,
                         SMEM_DYN);

    const int nBlkCvt = MROWS * DD / 4 / 256;  // 32768
    dim3 bT(32, 8);

    // 0) convert x to fp16
    cvt_half<<<nBlkCvt, 256>>>((const float4*)x, xh);

    // 1) transpose + split the six QKV weights (z-batched)
    {
        WtPtrs wp;
        const float* ws[6] = {sa_q_w, sa_k_w, sa_v_w, ta_q_w, ta_k_w, ta_v_w};
        for (int i = 0; i < 6; ++i) {
            wp.W[i] = ws[i];
            wp.Th[i] = wth + i * WSZ;
            wp.Tl[i] = wtl + i * WSZ;
        }
        wp.n = 6;
        wt_split_batch<<<dim3(32, 32, 6), bT>>>(wp);
    }

    // 2) fold o-proj into fuse: W1 = sa_o_w@fuse_top, W2 = ta_o_w@fuse_bot (z=2)
    fold2_kernel<<<dim3(8, 8, 2), 256>>>(sa_o_w, ta_o_w, fuse_w, W1, W2);

    // 3,4) combined bias
    bias_partial<<<dim3(4, 32), 256>>>(sa_o_b, ta_o_b, fuse_w, bcp);
    bias_reduce<<<4, 256>>>(bcp, fuse_b, bc);

    // 5) six QKV projections on tensor cores (fp16 outputs)
    QkvPtrs qp;
    __half* outs[6] = {qs, ks, vs, qt, kt, vt};
    const float* biases[6] = {sa_q_b, sa_k_b, sa_v_b, ta_q_b, ta_k_b, ta_v_b};
    for (int i = 0; i < 6; ++i) {
        qp.Bh[i] = wth + i * WSZ;
        qp.Bl[i] = wtl + i * WSZ;
        qp.bias[i] = biases[i];
        qp.C[i] = outs[i];
    }
    mma_gemm_qkv<<<dim3(DD / 128, MROWS / 128, 6), 256, SMEM_DYN>>>(xh, qp);

    // 6) transpose + split folded W1/W2 (z-batched)
    {
        WtPtrs wp;
        wp.W[0] = W1; wp.Th[0] = wth + 6 * WSZ; wp.Tl[0] = wtl + 6 * WSZ;
        wp.W[1] = W2; wp.Th[1] = wth + 7 * WSZ; wp.Tl[1] = wtl + 7 * WSZ;
        wp.n = 2;
        wt_split_batch<<<dim3(32, 32, 2), bT>>>(wp);
    }

    // 7) merged attention (fp16 in/out; temporal first, spatial backfills)
    attn_merged<<<BB * CLIPC * HH + BB * NCC / 2, 256>>>(
        qs, ks, vs, qt, kt, vt, mask, csh, cth);

    // 8) fused output: out = cs@W1t + ct@W2t + bc (single dual-K tensor GEMM)
    mma_gemm_dual<<<dim3(DD / 128, MROWS / 128), 256, SMEM_DYN>>>(
        csh, wth + 6 * WSZ, wtl + 6 * WSZ,
        cth, wth + 7 * WSZ, wtl + 7 * WSZ,
        bc, out);
}

// round 11
// speedup vs baseline: 1.5674x; 1.5674x over previous
#include <cuda_runtime.h>
#include <cuda_fp16.h>
#include <cstdint>

// Problem constants
#define BB 16
#define SS 2048
#define DD 1024
#define HH 16
#define DK 64
#define CLIPC 8
#define NCC 256
#define MROWS (BB * SS)  // 32768

// ---------------------------------------------------------------------------
// Scratch (static __device__ arrays; no allocation allowed)
// ---------------------------------------------------------------------------
__device__ float g_qs[MROWS * DD];
__device__ float g_ks[MROWS * DD];
__device__ float g_vs[MROWS * DD];
__device__ float g_qt[MROWS * DD];
__device__ float g_kt[MROWS * DD];
__device__ float g_vt[MROWS * DD];
__device__ float g_W1[DD * DD];
__device__ float g_W2[DD * DD];
__device__ float g_bc[DD];
__device__ float g_bcp[32][DD];

// fp16 buffers (A operands: hi only; weights: hi+lo)
__device__ __half g_xh[MROWS * DD];
__device__ __half g_csh[MROWS * DD];   // spatial attention out (fp16, direct)
__device__ __half g_cth[MROWS * DD];   // temporal attention out (fp16, direct)
// transposed+split weights: 0..5 = sa_q,sa_k,sa_v,ta_q,ta_k,ta_v; 6=W1; 7=W2
__device__ __half g_wth[8][DD * DD];
__device__ __half g_wtl[8][DD * DD];

// ---------------------------------------------------------------------------
// Packed f32x2 helpers
// ---------------------------------------------------------------------------
__device__ __forceinline__ unsigned long long pk2(float lo, float hi) {
    unsigned long long r;
    asm("mov.b64 %0, {%1, %2};" : "=l"(r) : "f"(lo), "f"(hi));
    return r;
}
__device__ __forceinline__ void fma2(unsigned long long& d, unsigned long long a,
                                     unsigned long long b) {
    asm("fma.rn.f32x2 %0, %1, %2, %0;" : "+l"(d) : "l"(a), "l"(b));
}
__device__ __forceinline__ void mul2(unsigned long long& d, unsigned long long a) {
    asm("mul.rn.f32x2 %0, %0, %1;" : "+l"(d) : "l"(a));
}
__device__ __forceinline__ float2 upk(unsigned long long v) {
    float2 f;
    asm("mov.b64 {%0, %1}, %2;" : "=f"(f.x), "=f"(f.y) : "l"(v));
    return f;
}

// ---------------------------------------------------------------------------
// mma.sync helpers (base PTX ISA — compiles at .target sm_103)
// ---------------------------------------------------------------------------
__device__ __forceinline__ uint32_t smem_u32(const void* p) {
    uint32_t a;
    asm("{ .reg .u64 t; cvta.to.shared.u64 t, %1; cvt.u32.u64 %0, t; }"
        : "=r"(a) : "l"(p));
    return a;
}
__device__ __forceinline__ void ldsm4(uint32_t* r, uint32_t addr) {
    asm volatile(
        "ldmatrix.sync.aligned.m8n8.x4.shared.b16 {%0,%1,%2,%3}, [%4];"
        : "=r"(r[0]), "=r"(r[1]), "=r"(r[2]), "=r"(r[3]) : "r"(addr));
}
__device__ __forceinline__ void mma16816(float* d, const uint32_t* a,
                                         const uint32_t* b) {
    asm volatile(
        "mma.sync.aligned.m16n8k16.row.col.f32.f16.f16.f32 "
        "{%0,%1,%2,%3}, {%4,%5,%6,%7}, {%8,%9}, {%0,%1,%2,%3};"
        : "+f"(d[0]), "+f"(d[1]), "+f"(d[2]), "+f"(d[3])
        : "r"(a[0]), "r"(a[1]), "r"(a[2]), "r"(a[3]), "r"(b[0]), "r"(b[1]));
}
#define CPASYNC16(dst, src) \
    asm volatile("cp.async.cg.shared.global [%0], [%1], 16;" :: "r"(dst), "l"(src))
#define CPCOMMIT() asm volatile("cp.async.commit_group;" ::: "memory")
#define CPWAIT2() asm volatile("cp.async.wait_group 2;" ::: "memory")

// smem geometry: row pitch 80B (40 fp16), conflict-free for ldmatrix.
#define PITCHB 80
#define TILEB (128 * PITCHB)     // 10240 bytes per operand tile
#define STAGEB (3 * TILEB)       // Ah, Bh, Bl
#define NSTAGE 3
#define SMEM_DYN (NSTAGE * STAGEB)  // 92160 bytes

// ---------------------------------------------------------------------------
// fp16 2-pass GEMM core: C = Ah*Bh^T + Ah*Bl^T + bias (fp32 output)
// CTA tile 128x128, BK=32, 8 warps (4M x 2N), 3-stage cp.async. (R4 config)
// ---------------------------------------------------------------------------
struct GSrc {
    const __half *Ah, *Bh, *Bl;
};

__device__ __forceinline__ void mma_core(
    GSrc s0, GSrc s1, int nchunk,
    const float* __restrict__ bias, float* __restrict__ C, int bm, int bn)
{
    extern __shared__ char sm[];
    const uint32_t sbase = smem_u32(sm);
    const int tid = threadIdx.x, wid = tid >> 5, l = tid & 31;
    const int wm = (wid & 3) * 32;   // warp row offset in CTA tile
    const int wn = (wid >> 2) * 64;  // warp col offset

    auto issue = [&](int kc) {
        if (kc < nchunk) {
            const GSrc& s = (kc < 32) ? s0 : s1;
            const int kl = kc & 31;
            const uint32_t st = sbase + (kc % NSTAGE) * STAGEB;
            const __half* srcs[3] = {s.Ah, s.Bh, s.Bl};
#pragma unroll
            for (int t3 = 0; t3 < 3; ++t3) {
                const int rb = (t3 == 0) ? bm : bn;
                const uint32_t doff = st + t3 * TILEB;
                const __half* sp = srcs[t3];
#pragma unroll
                for (int j = 0; j < 2; ++j) {
                    int c = tid + j * 256;
                    int row = c >> 2, pos = c & 3;
                    uint32_t dst = doff + row * PITCHB + pos * 16;
                    const void* src = sp + (size_t)(rb + row) * DD + kl * 32 + pos * 8;
                    CPASYNC16(dst, src);
                }
            }
        }
        CPCOMMIT();
    };

    issue(0);
    issue(1);
    issue(2);

    float acc[2][8][4];
#pragma unroll
    for (int mi = 0; mi < 2; ++mi)
#pragma unroll
        for (int ni = 0; ni < 8; ++ni)
#pragma unroll
            for (int f = 0; f < 4; ++f) acc[mi][ni][f] = 0.0f;

    const uint32_t m8 = l >> 3;
    const uint32_t laneArow = (m8 & 1) * 8 + (l & 7);
    const uint32_t laneAkb = (m8 >> 1) * 16;
    const uint32_t laneBrow = (m8 >> 1) * 8 + (l & 7);
    const uint32_t laneBkb = (m8 & 1) * 16;

    for (int kc = 0; kc < nchunk; ++kc) {
        CPWAIT2();
        __syncthreads();
        const uint32_t st = sbase + (kc % NSTAGE) * STAGEB;
#pragma unroll
        for (int ks = 0; ks < 2; ++ks) {
            const uint32_t kbyte = ks * 32;
            uint32_t ah[2][4];
#pragma unroll
            for (int mi = 0; mi < 2; ++mi) {
                uint32_t r = wm + mi * 16 + laneArow;
                ldsm4(ah[mi], st + 0 * TILEB + r * PITCHB + kbyte + laneAkb);
            }
            uint32_t bh[8][2], bl[8][2];
#pragma unroll
            for (int bi = 0; bi < 4; ++bi) {
                uint32_t r = wn + bi * 16 + laneBrow;
                uint32_t q[4];
                ldsm4(q, st + 1 * TILEB + r * PITCHB + kbyte + laneBkb);
                bh[bi * 2][0] = q[0]; bh[bi * 2][1] = q[1];
                bh[bi * 2 + 1][0] = q[2]; bh[bi * 2 + 1][1] = q[3];
                ldsm4(q, st + 2 * TILEB + r * PITCHB + kbyte + laneBkb);
                bl[bi * 2][0] = q[0]; bl[bi * 2][1] = q[1];
                bl[bi * 2 + 1][0] = q[2]; bl[bi * 2 + 1][1] = q[3];
            }
#pragma unroll
            for (int mi = 0; mi < 2; ++mi)
#pragma unroll
                for (int ni = 0; ni < 8; ++ni) {
                    mma16816(acc[mi][ni], ah[mi], bh[ni]);
                    mma16816(acc[mi][ni], ah[mi], bl[ni]);
                }
        }
        __syncthreads();
        issue(kc + NSTAGE);
    }

    // epilogue
#pragma unroll
    for (int mi = 0; mi < 2; ++mi) {
        const int r0 = bm + wm + mi * 16 + (l >> 2);
#pragma unroll
        for (int ni = 0; ni < 8; ++ni) {
            const int c = bn + wn + ni * 8 + (l & 3) * 2;
            const float b0v = bias[c], b1v = bias[c + 1];
            float2 v0, v1;
            v0.x = acc[mi][ni][0] + b0v;
            v0.y = acc[mi][ni][1] + b1v;
            v1.x = acc[mi][ni][2] + b0v;
            v1.y = acc[mi][ni][3] + b1v;
            *(float2*)(C + (size_t)r0 * DD + c) = v0;
            *(float2*)(C + (size_t)(r0 + 8) * DD + c) = v1;
        }
    }
}

// batched QKV: z selects weight/bias/output; A = x (shared)
struct QkvPtrs {
    const __half* Bh[6];
    const __half* Bl[6];
    const float* bias[6];
    float* C[6];
};

__global__ __launch_bounds__(256) void mma_gemm_qkv(
    const __half* __restrict__ Ah, QkvPtrs p)
{
    int z = blockIdx.z;
    GSrc s{Ah, p.Bh[z], p.Bl[z]};
    mma_core(s, s, 32, p.bias[z], p.C[z], blockIdx.y * 128, blockIdx.x * 128);
}

__global__ __launch_bounds__(256) void mma_gemm_dual(
    const __half* A0h, const __half* B0h, const __half* B0l,
    const __half* A1h, const __half* B1h, const __half* B1l,
    const float* bias, float* C)
{
    GSrc s0{A0h, B0h, B0l};
    GSrc s1{A1h, B1h, B1l};
    mma_core(s0, s1, 64, bias, C, blockIdx.y * 128, blockIdx.x * 128);
}

// ---------------------------------------------------------------------------
// fp32 -> fp16 convert (hi only), vectorized
// ---------------------------------------------------------------------------
__global__ __launch_bounds__(256) void cvt_half(
    const float4* __restrict__ X, __half* __restrict__ H)
{
    size_t idx = (size_t)blockIdx.x * 256 + threadIdx.x;
    float4 v = X[idx];
    __half h[4];
    h[0] = __float2half(v.x);
    h[1] = __float2half(v.y);
    h[2] = __float2half(v.z);
    h[3] = __float2half(v.w);
    *(uint2*)(H + idx * 4) = *(uint2*)h;
}

// ---------------------------------------------------------------------------
// Weight transpose + split (z-batched): W[K=1024, N=1024] fp32 -> Th/Tl [N,K]
// ---------------------------------------------------------------------------
struct WtPtrs {
    const float* W[6];
    __half* Th[6];
    __half* Tl[6];
    int n;
};

__device__ __forceinline__ void wt_split_body(
    const float* __restrict__ W, __half* __restrict__ Th,
    __half* __restrict__ Tl)
{
    __shared__ float t[32][33];
    int tx = threadIdx.x, ty = threadIdx.y;
    int n0 = blockIdx.x * 32, k0 = blockIdx.y * 32;
#pragma unroll
    for (int j = 0; j < 4; ++j) {
        int k = k0 + ty + j * 8;
        t[ty + j * 8][tx] = W[(size_t)k * DD + n0 + tx];
    }
    __syncthreads();
#pragma unroll
    for (int j = 0; j < 4; ++j) {
        int n = n0 + ty + j * 8;
        int k = k0 + tx;
        float v = t[tx][ty + j * 8];
        __half h = __float2half(v);
        __half lo = __float2half(v - __half2float(h));
        Th[(size_t)n * DD + k] = h;
        Tl[(size_t)n * DD + k] = lo;
    }
}

__global__ void wt_split_batch(WtPtrs p)
{
    int z = blockIdx.z;
    wt_split_body(p.W[z], p.Th[z], p.Tl[z]);
}

// ---------------------------------------------------------------------------
// Scalar fp32 GEMM body (fixed 1024x1024x1024, no bias) + z=2 fold kernel
// ---------------------------------------------------------------------------
__device__ __forceinline__ void gemm_scalar_body(
    const float* __restrict__ A, const float* __restrict__ B,
    float* __restrict__ C)
{
    __shared__ float As[16][128];
    __shared__ float Bs[16][128];
    const int tid = threadIdx.x;
    const int bm = blockIdx.y * 128;
    const int bn = blockIdx.x * 128;
    const int tm = (tid >> 4) << 3;
    const int tn = (tid & 15) << 3;

    unsigned long long acc2[8][4];
#pragma unroll
    for (int i = 0; i < 8; ++i)
#pragma unroll
        for (int j = 0; j < 4; ++j) acc2[i][j] = 0ull;

    const int nk = DD >> 4;
    float4 aR[2], bR[2];
    auto loadTile = [&](int kt) {
        const int k0 = kt << 4;
#pragma unroll
        for (int j = 0; j < 2; ++j) {
            int i = tid + (j << 8);
            int ar = i >> 2, ac = (i & 3) << 2;
            aR[j] = *(const float4*)(A + (size_t)(bm + ar) * DD + k0 + ac);
            int br = i >> 5, bc = (i & 31) << 2;
            bR[j] = *(const float4*)(B + (size_t)(k0 + br) * DD + bn + bc);
        }
    };
    auto storeTile = [&]() {
#pragma unroll
        for (int j = 0; j < 2; ++j) {
            int i = tid + (j << 8);
            int ar = i >> 2, ac = (i & 3) << 2;
            As[ac + 0][ar] = aR[j].x;
            As[ac + 1][ar] = aR[j].y;
            As[ac + 2][ar] = aR[j].z;
            As[ac + 3][ar] = aR[j].w;
            int br = i >> 5, bc = (i & 31) << 2;
            *(float4*)&Bs[br][bc] = bR[j];
        }
    };
    loadTile(0);
    storeTile();
    __syncthreads();
    for (int kt = 0; kt < nk; ++kt) {
        if (kt + 1 < nk) loadTile(kt + 1);
#pragma unroll
        for (int k = 0; k < 16; ++k) {
            float4 a0 = *(const float4*)&As[k][tm];
            float4 a1 = *(const float4*)&As[k][tm + 4];
            float4 b0 = *(const float4*)&Bs[k][tn];
            float4 b1 = *(const float4*)&Bs[k][tn + 4];
            unsigned long long rbp[4] = {pk2(b0.x, b0.y), pk2(b0.z, b0.w),
                                         pk2(b1.x, b1.y), pk2(b1.z, b1.w)};
            float ra[8] = {a0.x, a0.y, a0.z, a0.w, a1.x, a1.y, a1.z, a1.w};
#pragma unroll
            for (int i = 0; i < 8; ++i) {
                unsigned long long aa = pk2(ra[i], ra[i]);
#pragma unroll
                for (int jp = 0; jp < 4; ++jp) fma2(acc2[i][jp], aa, rbp[jp]);
            }
        }
        __syncthreads();
        if (kt + 1 < nk) {
            storeTile();
            __syncthreads();
        }
    }
#pragma unroll
    for (int i = 0; i < 8; ++i) {
        float* crow = C + (size_t)(bm + tm + i) * DD + bn + tn;
#pragma unroll
        for (int jp = 0; jp < 4; ++jp) {
            float2 f = upk(acc2[i][jp]);
            *(float2*)(crow + 2 * jp) = f;
        }
    }
}

__global__ __launch_bounds__(256) void fold2_kernel(
    const float* __restrict__ sa_o_w, const float* __restrict__ ta_o_w,
    const float* __restrict__ fuse_w, float* __restrict__ W1,
    float* __restrict__ W2)
{
    if (blockIdx.z == 0)
        gemm_scalar_body(sa_o_w, fuse_w, W1);
    else
        gemm_scalar_body(ta_o_w, fuse_w + (size_t)DD * DD, W2);
}

// ---------------------------------------------------------------------------
// Merged attention: blocks [0,2048) temporal, [2048,4096) spatial.
// fp32 q/k/v in, fp16 out. (R9-verified)
// ---------------------------------------------------------------------------
__device__ __forceinline__ void temporal_body(
    const float* __restrict__ Q, const float* __restrict__ Kp,
    const float* __restrict__ Vp, const int* __restrict__ mask,
    __half* __restrict__ O, int gid)
{
    __shared__ float Ks[64][64];
    __shared__ float Vs[64][64];
    __shared__ int Msk[64];

    int h = gid & 15;
    int clip = (gid >> 4) & 7;
    int b = gid >> 7;
    const size_t base = ((size_t)b * SS + clip) * DD + h * DK;
    const int RS = CLIPC * DD;

    int cq = threadIdx.x;
    unsigned long long qv[32];
    {
        const unsigned long long* qp =
            (const unsigned long long*)(Q + base + (size_t)cq * RS);
#pragma unroll
        for (int i = 0; i < 32; ++i) qv[i] = qp[i];
    }
    unsigned long long acc[32];
#pragma unroll
    for (int i = 0; i < 32; ++i) acc[i] = 0ull;
    float mmax = -1e30f, l = 0.f;

    const int lr = threadIdx.x >> 2;
    const int lc = (threadIdx.x & 3) << 4;

    for (int kt = 0; kt < 4; ++kt) {
        __syncthreads();
        {
            const float* krow = Kp + base + (size_t)(kt * 64 + lr) * RS;
            const float* vrow = Vp + base + (size_t)(kt * 64 + lr) * RS;
#pragma unroll
            for (int j = 0; j < 4; ++j) {
                *(float4*)&Ks[lr][lc + 4 * j] = *(const float4*)(krow + lc + 4 * j);
                *(float4*)&Vs[lr][lc + 4 * j] = *(const float4*)(vrow + lc + 4 * j);
            }
            if (threadIdx.x < 64)
                Msk[threadIdx.x] =
                    mask[(size_t)b * SS + (size_t)(kt * 64 + threadIdx.x) * CLIPC + clip];
        }
        __syncthreads();

        for (int kk = 0; kk < 64; ++kk) {
            if (Msk[kk] == 0) continue;
            const unsigned long long* kr = (const unsigned long long*)&Ks[kk][0];
            unsigned long long d2 = 0ull;
#pragma unroll
            for (int i = 0; i < 32; ++i) fma2(d2, qv[i], kr[i]);
            float2 dd = upk(d2);
            float s = (dd.x + dd.y) * 0.125f;
            if (s > mmax) {
                float corr = __expf(mmax - s);
                unsigned long long cc = pk2(corr, corr);
#pragma unroll
                for (int i = 0; i < 32; ++i) mul2(acc[i], cc);
                l *= corr;
                mmax = s;
            }
            float p = __expf(s - mmax);
            l += p;
            unsigned long long pp = pk2(p, p);
            const unsigned long long* vr = (const unsigned long long*)&Vs[kk][0];
#pragma unroll
            for (int i = 0; i < 32; ++i) fma2(acc[i], pp, vr[i]);
        }
    }
    float inv = 1.0f / l;
    __half2* op = (__half2*)(O + base + (size_t)cq * RS);
#pragma unroll
    for (int i = 0; i < 32; ++i) {
        float2 f = upk(acc[i]);
        op[i] = __floats2half2_rn(f.x * inv, f.y * inv);
    }
}

__device__ __forceinline__ void spatial_body(
    const float* __restrict__ Q, const float* __restrict__ Kp,
    const float* __restrict__ Vp, const int* __restrict__ mask,
    __half* __restrict__ O, int blk)
{
    int unit = blk * 2 + (threadIdx.x >> 7);
    int t = threadIdx.x & 127;
    int h = t >> 3, qi = t & 7;
    int b = unit >> 8, nc = unit & 255;
    size_t rowBase = (size_t)b * SS + (size_t)nc * CLIPC;

    unsigned long long qv[32];
    {
        const unsigned long long* qp =
            (const unsigned long long*)(Q + (rowBase + qi) * DD + h * DK);
#pragma unroll
        for (int i = 0; i < 32; ++i) qv[i] = qp[i];
    }
    const float* kbase = Kp + rowBase * DD + h * DK;
    float sc[8];
    float mx = -1e30f;
#pragma unroll
    for (int kk = 0; kk < 8; ++kk) {
        const unsigned long long* kr =
            (const unsigned long long*)(kbase + (size_t)kk * DD);
        unsigned long long d2 = 0ull;
#pragma unroll
        for (int i = 0; i < 32; ++i) fma2(d2, qv[i], kr[i]);
        float2 dd = upk(d2);
        float s = (dd.x + dd.y) * 0.125f;
        sc[kk] = (mask[rowBase + kk] != 0) ? s : -1e30f;
        mx = fmaxf(mx, sc[kk]);
    }
    float p[8], sum = 0.f;
#pragma unroll
    for (int kk = 0; kk < 8; ++kk) {
        p[kk] = __expf(sc[kk] - mx);
        sum += p[kk];
    }
    float inv = 1.0f / sum;
    unsigned long long acc[32];
#pragma unroll
    for (int i = 0; i < 32; ++i) acc[i] = 0ull;
    const float* vbase = Vp + rowBase * DD + h * DK;
#pragma unroll
    for (int kk = 0; kk < 8; ++kk) {
        unsigned long long pp = pk2(p[kk], p[kk]);
        const unsigned long long* vr =
            (const unsigned long long*)(vbase + (size_t)kk * DD);
#pragma unroll
        for (int i = 0; i < 32; ++i) fma2(acc[i], pp, vr[i]);
    }
    __half2* op = (__half2*)(O + (rowBase + qi) * DD + h * DK);
#pragma unroll
    for (int i = 0; i < 32; ++i) {
        float2 f = upk(acc[i]);
        op[i] = __floats2half2_rn(f.x * inv, f.y * inv);
    }
}

__global__ __launch_bounds__(256) void attn_merged(
    const float* __restrict__ qs, const float* __restrict__ ks,
    const float* __restrict__ vs, const float* __restrict__ qt,
    const float* __restrict__ kt, const float* __restrict__ vt,
    const int* __restrict__ mask, __half* __restrict__ csh,
    __half* __restrict__ cth)
{
    int blk = blockIdx.x;
    if (blk < BB * CLIPC * HH) {
        temporal_body(qt, kt, vt, mask, cth, blk);  // long blocks first
    } else {
        spatial_body(qs, ks, vs, mask, csh, blk - BB * CLIPC * HH);
    }
}

// ---------------------------------------------------------------------------
// bias combine, parallel 2-stage
// ---------------------------------------------------------------------------
__global__ void bias_partial(const float* __restrict__ sab,
                             const float* __restrict__ tab,
                             const float* __restrict__ fw,
                             float* __restrict__ part)
{
    int n = blockIdx.x * 256 + threadIdx.x;
    int j = blockIdx.y;
    int k0 = j * 64;
    float s = 0.f;
#pragma unroll 8
    for (int k = k0; k < k0 + 64; ++k) {
        float coef = (k < DD) ? sab[k] : tab[k - DD];
        s += coef * fw[(size_t)k * DD + n];
    }
    part[(size_t)j * DD + n] = s;
}

__global__ void bias_reduce(const float* __restrict__ part,
                            const float* __restrict__ fb,
                            float* __restrict__ bc)
{
    int n = blockIdx.x * 256 + threadIdx.x;
    float s = fb[n];
#pragma unroll
    for (int j = 0; j < 32; ++j) s += part[(size_t)j * DD + n];
    bc[n] = s;
}

// ---------------------------------------------------------------------------
// Launch sequence: main chain on default stream, dual-GEMM prep chain forked
// onto a side stream (event fork/join — capturable pattern).
// ---------------------------------------------------------------------------
extern "C" void kernel_launch(void* const* d_in, const int* in_sizes, int n_in,
                              void* d_out, int out_size)
{
    const float* x       = (const float*)d_in[0];
    const int*   mask    = (const int*)d_in[1];
    const float* sa_q_w  = (const float*)d_in[2];
    const float* sa_q_b  = (const float*)d_in[3];
    const float* sa_k_w  = (const float*)d_in[4];
    const float* sa_k_b  = (const float*)d_in[5];
    const float* sa_v_w  = (const float*)d_in[6];
    const float* sa_v_b  = (const float*)d_in[7];
    const float* sa_o_w  = (const float*)d_in[8];
    const float* sa_o_b  = (const float*)d_in[9];
    const float* ta_q_w  = (const float*)d_in[10];
    const float* ta_q_b  = (const float*)d_in[11];
    const float* ta_k_w  = (const float*)d_in[12];
    const float* ta_k_b  = (const float*)d_in[13];
    const float* ta_v_w  = (const float*)d_in[14];
    const float* ta_v_b  = (const float*)d_in[15];
    const float* ta_o_w  = (const float*)d_in[16];
    const float* ta_o_b  = (const float*)d_in[17];
    const float* fuse_w  = (const float*)d_in[18];
    const float* fuse_b  = (const float*)d_in[19];
    float* out = (float*)d_out;

    float *qs, *ks, *vs, *qt, *kt, *vt, *W1, *W2, *bc, *bcp;
    cudaGetSymbolAddress((void**)&qs, g_qs);
    cudaGetSymbolAddress((void**)&ks, g_ks);
    cudaGetSymbolAddress((void**)&vs, g_vs);
    cudaGetSymbolAddress((void**)&qt, g_qt);
    cudaGetSymbolAddress((void**)&kt, g_kt);
    cudaGetSymbolAddress((void**)&vt, g_vt);
    cudaGetSymbolAddress((void**)&W1, g_W1);
    cudaGetSymbolAddress((void**)&W2, g_W2);
    cudaGetSymbolAddress((void**)&bc, g_bc);
    cudaGetSymbolAddress((void**)&bcp, g_bcp);

    __half *xh, *csh, *cth, *wth, *wtl;
    cudaGetSymbolAddress((void**)&xh, g_xh);
    cudaGetSymbolAddress((void**)&csh, g_csh);
    cudaGetSymbolAddress((void**)&cth, g_cth);
    cudaGetSymbolAddress((void**)&wth, g_wth);
    cudaGetSymbolAddress((void**)&wtl, g_wtl);
    const size_t WSZ = (size_t)DD * DD;

    cudaFuncSetAttribute(mma_gemm_qkv, cudaFuncAttributeMaxDynamicSharedMemorySize,
                         SMEM_DYN);
    cudaFuncSetAttribute(mma_gemm_dual, cudaFuncAttributeMaxDynamicSharedMemorySize,
                         SMEM_DYN);

    // Persistent side stream + events (created once, on the first —
    // uncaptured — correctness call; reused identically every call).
    static cudaStream_t s1 = nullptr;
    static cudaEvent_t evFork = nullptr, evJoin = nullptr;
    if (!s1) {
        cudaStreamCreateWithFlags(&s1, cudaStreamNonBlocking);
        cudaEventCreateWithFlags(&evFork, cudaEventDisableTiming);
        cudaEventCreateWithFlags(&evJoin, cudaEventDisableTiming);
    }

    const int nBlkCvt = MROWS * DD / 4 / 256;  // 32768
    dim3 bT(32, 8);

    // ---- fork: side chain (prep for the final dual GEMM) ----
    cudaEventRecord(evFork, 0);
    cudaStreamWaitEvent(s1, evFork, 0);

    fold2_kernel<<<dim3(8, 8, 2), 256, 0, s1>>>(sa_o_w, ta_o_w, fuse_w, W1, W2);
    bias_partial<<<dim3(4, 32), 256, 0, s1>>>(sa_o_b, ta_o_b, fuse_w, bcp);
    bias_reduce<<<4, 256, 0, s1>>>(bcp, fuse_b, bc);
    {
        WtPtrs wp;
        wp.W[0] = W1; wp.Th[0] = wth + 6 * WSZ; wp.Tl[0] = wtl + 6 * WSZ;
        wp.W[1] = W2; wp.Th[1] = wth + 7 * WSZ; wp.Tl[1] = wtl + 7 * WSZ;
        wp.n = 2;
        wt_split_batch<<<dim3(32, 32, 2), bT, 0, s1>>>(wp);
    }
    cudaEventRecord(evJoin, s1);

    // ---- main chain (default stream) ----
    cvt_half<<<nBlkCvt, 256>>>((const float4*)x, xh);
    {
        WtPtrs wp;
        const float* ws[6] = {sa_q_w, sa_k_w, sa_v_w, ta_q_w, ta_k_w, ta_v_w};
        for (int i = 0; i < 6; ++i) {
            wp.W[i] = ws[i];
            wp.Th[i] = wth + i * WSZ;
            wp.Tl[i] = wtl + i * WSZ;
        }
        wp.n = 6;
        wt_split_batch<<<dim3(32, 32, 6), bT>>>(wp);
    }

    QkvPtrs qp;
    float* outs[6] = {qs, ks, vs, qt, kt, vt};
    const float* biases[6] = {sa_q_b, sa_k_b, sa_v_b, ta_q_b, ta_k_b, ta_v_b};
    for (int i = 0; i < 6; ++i) {
        qp.Bh[i] = wth + i * WSZ;
        qp.Bl[i] = wtl + i * WSZ;
        qp.bias[i] = biases[i];
        qp.C[i] = outs[i];
    }
    mma_gemm_qkv<<<dim3(DD / 128, MROWS / 128, 6), 256, SMEM_DYN>>>(xh, qp);

    attn_merged<<<BB * CLIPC * HH + BB * NCC / 2, 256>>>(
        qs, ks, vs, qt, kt, vt, mask, csh, cth);

    // ---- join, then final dual GEMM ----
    cudaStreamWaitEvent(0, evJoin, 0);
    mma_gemm_dual<<<dim3(DD / 128, MROWS / 128), 256, SMEM_DYN>>>(
        csh, wth + 6 * WSZ, wtl + 6 * WSZ,
        cth, wth + 7 * WSZ, wtl + 7 * WSZ,
        bc, out);
}

// round 12
// speedup vs baseline: 2.0959x; 1.3372x over previous
#include <cuda_runtime.h>
#include <cuda_fp16.h>
#include <cstdint>

// Problem constants
#define BB 16
#define SS 2048
#define DD 1024
#define HH 16
#define DK 64
#define CLIPC 8
#define NCC 256
#define MROWS (BB * SS)  // 32768

// ---------------------------------------------------------------------------
// Scratch (static __device__ arrays; no allocation allowed)
// ---------------------------------------------------------------------------
__device__ float g_qs[MROWS * DD];
__device__ float g_ks[MROWS * DD];
__device__ float g_vs[MROWS * DD];
__device__ float g_qt[MROWS * DD];
__device__ float g_kt[MROWS * DD];
__device__ float g_vt[MROWS * DD];
__device__ float g_W1[DD * DD];
__device__ float g_W2[DD * DD];
__device__ float g_bc[DD];
__device__ float g_bcp[32][DD];

// fp16 buffers
__device__ __half g_xh[MROWS * DD];
__device__ __half g_csh[MROWS * DD];   // spatial attention out (fp16, direct)
__device__ __half g_cth[MROWS * DD];   // temporal attention out (fp16, direct)
// transposed fp16 weights: 0..5 = sa_q,sa_k,sa_v,ta_q,ta_k,ta_v; 6=W1; 7=W2
__device__ __half g_wth[8][DD * DD];

// ---------------------------------------------------------------------------
// Packed f32x2 helpers
// ---------------------------------------------------------------------------
__device__ __forceinline__ unsigned long long pk2(float lo, float hi) {
    unsigned long long r;
    asm("mov.b64 %0, {%1, %2};" : "=l"(r) : "f"(lo), "f"(hi));
    return r;
}
__device__ __forceinline__ void fma2(unsigned long long& d, unsigned long long a,
                                     unsigned long long b) {
    asm("fma.rn.f32x2 %0, %1, %2, %0;" : "+l"(d) : "l"(a), "l"(b));
}
__device__ __forceinline__ void mul2(unsigned long long& d, unsigned long long a) {
    asm("mul.rn.f32x2 %0, %0, %1;" : "+l"(d) : "l"(a));
}
__device__ __forceinline__ float2 upk(unsigned long long v) {
    float2 f;
    asm("mov.b64 {%0, %1}, %2;" : "=f"(f.x), "=f"(f.y) : "l"(v));
    return f;
}

// ---------------------------------------------------------------------------
// mma.sync helpers (base PTX ISA — compiles at .target sm_103)
// ---------------------------------------------------------------------------
__device__ __forceinline__ uint32_t smem_u32(const void* p) {
    uint32_t a;
    asm("{ .reg .u64 t; cvta.to.shared.u64 t, %1; cvt.u32.u64 %0, t; }"
        : "=r"(a) : "l"(p));
    return a;
}
__device__ __forceinline__ void ldsm4(uint32_t* r, uint32_t addr) {
    asm volatile(
        "ldmatrix.sync.aligned.m8n8.x4.shared.b16 {%0,%1,%2,%3}, [%4];"
        : "=r"(r[0]), "=r"(r[1]), "=r"(r[2]), "=r"(r[3]) : "r"(addr));
}
__device__ __forceinline__ void mma16816(float* d, const uint32_t* a,
                                         const uint32_t* b) {
    asm volatile(
        "mma.sync.aligned.m16n8k16.row.col.f32.f16.f16.f32 "
        "{%0,%1,%2,%3}, {%4,%5,%6,%7}, {%8,%9}, {%0,%1,%2,%3};"
        : "+f"(d[0]), "+f"(d[1]), "+f"(d[2]), "+f"(d[3])
        : "r"(a[0]), "r"(a[1]), "r"(a[2]), "r"(a[3]), "r"(b[0]), "r"(b[1]));
}
#define CPASYNC16(dst, src) \
    asm volatile("cp.async.cg.shared.global [%0], [%1], 16;" :: "r"(dst), "l"(src))
#define CPCOMMIT() asm volatile("cp.async.commit_group;" ::: "memory")
#define CPWAIT2() asm volatile("cp.async.wait_group 2;" ::: "memory")

// smem geometry: row pitch 80B (40 fp16), conflict-free for ldmatrix.
#define PITCHB 80
#define TILEB (128 * PITCHB)     // 10240 bytes per operand tile
#define STAGEB (2 * TILEB)       // Ah, Bh (1-pass: no Bl)
#define NSTAGE 3
#define SMEM_DYN (NSTAGE * STAGEB)  // 61440 bytes

// ---------------------------------------------------------------------------
// fp16 1-pass GEMM core: C = Ah*Bh^T + bias (fp32 accum/output).
// CTA tile 128x128, BK=32, 8 warps (4M x 2N), 3-stage cp.async.
// MMA-bound at the legacy-HMMA floor; 1-pass halves the MMA count vs 2-pass.
// ---------------------------------------------------------------------------
struct GSrc {
    const __half *Ah, *Bh;
};

__device__ __forceinline__ void mma_core(
    GSrc s0, GSrc s1, int nchunk,
    const float* __restrict__ bias, float* __restrict__ C, int bm, int bn)
{
    extern __shared__ char sm[];
    const uint32_t sbase = smem_u32(sm);
    const int tid = threadIdx.x, wid = tid >> 5, l = tid & 31;
    const int wm = (wid & 3) * 32;   // warp row offset in CTA tile
    const int wn = (wid >> 2) * 64;  // warp col offset

    // stage copy: 2 tiles x 512 16B-chunks, 2 chunks per thread per tile
    auto issue = [&](int kc) {
        if (kc < nchunk) {
            const GSrc& s = (kc < 32) ? s0 : s1;
            const int kl = kc & 31;
            const uint32_t st = sbase + (kc % NSTAGE) * STAGEB;
            const __half* srcs[2] = {s.Ah, s.Bh};
#pragma unroll
            for (int t2 = 0; t2 < 2; ++t2) {
                const int rb = (t2 == 0) ? bm : bn;
                const uint32_t doff = st + t2 * TILEB;
                const __half* sp = srcs[t2];
#pragma unroll
                for (int j = 0; j < 2; ++j) {
                    int c = tid + j * 256;
                    int row = c >> 2, pos = c & 3;
                    uint32_t dst = doff + row * PITCHB + pos * 16;
                    const void* src = sp + (size_t)(rb + row) * DD + kl * 32 + pos * 8;
                    CPASYNC16(dst, src);
                }
            }
        }
        CPCOMMIT();
    };

    issue(0);
    issue(1);
    issue(2);

    float acc[2][8][4];
#pragma unroll
    for (int mi = 0; mi < 2; ++mi)
#pragma unroll
        for (int ni = 0; ni < 8; ++ni)
#pragma unroll
            for (int f = 0; f < 4; ++f) acc[mi][ni][f] = 0.0f;

    const uint32_t m8 = l >> 3;
    const uint32_t laneArow = (m8 & 1) * 8 + (l & 7);
    const uint32_t laneAkb = (m8 >> 1) * 16;
    const uint32_t laneBrow = (m8 >> 1) * 8 + (l & 7);
    const uint32_t laneBkb = (m8 & 1) * 16;

    for (int kc = 0; kc < nchunk; ++kc) {
        CPWAIT2();
        __syncthreads();
        const uint32_t st = sbase + (kc % NSTAGE) * STAGEB;
#pragma unroll
        for (int ks = 0; ks < 2; ++ks) {
            const uint32_t kbyte = ks * 32;
            uint32_t ah[2][4];
#pragma unroll
            for (int mi = 0; mi < 2; ++mi) {
                uint32_t r = wm + mi * 16 + laneArow;
                ldsm4(ah[mi], st + 0 * TILEB + r * PITCHB + kbyte + laneAkb);
            }
            uint32_t bh[8][2];
#pragma unroll
            for (int bi = 0; bi < 4; ++bi) {
                uint32_t r = wn + bi * 16 + laneBrow;
                uint32_t q[4];
                ldsm4(q, st + 1 * TILEB + r * PITCHB + kbyte + laneBkb);
                bh[bi * 2][0] = q[0]; bh[bi * 2][1] = q[1];
                bh[bi * 2 + 1][0] = q[2]; bh[bi * 2 + 1][1] = q[3];
            }
#pragma unroll
            for (int mi = 0; mi < 2; ++mi)
#pragma unroll
                for (int ni = 0; ni < 8; ++ni)
                    mma16816(acc[mi][ni], ah[mi], bh[ni]);
        }
        __syncthreads();
        issue(kc + NSTAGE);
    }

    // epilogue
#pragma unroll
    for (int mi = 0; mi < 2; ++mi) {
        const int r0 = bm + wm + mi * 16 + (l >> 2);
#pragma unroll
        for (int ni = 0; ni < 8; ++ni) {
            const int c = bn + wn + ni * 8 + (l & 3) * 2;
            const float b0v = bias[c], b1v = bias[c + 1];
            float2 v0, v1;
            v0.x = acc[mi][ni][0] + b0v;
            v0.y = acc[mi][ni][1] + b1v;
            v1.x = acc[mi][ni][2] + b0v;
            v1.y = acc[mi][ni][3] + b1v;
            *(float2*)(C + (size_t)r0 * DD + c) = v0;
            *(float2*)(C + (size_t)(r0 + 8) * DD + c) = v1;
        }
    }
}

// batched QKV: z selects weight/bias/output; A = x (shared)
struct QkvPtrs {
    const __half* Bh[6];
    const float* bias[6];
    float* C[6];
};

__global__ __launch_bounds__(256) void mma_gemm_qkv(
    const __half* __restrict__ Ah, QkvPtrs p)
{
    int z = blockIdx.z;
    GSrc s{Ah, p.Bh[z]};
    mma_core(s, s, 32, p.bias[z], p.C[z], blockIdx.y * 128, blockIdx.x * 128);
}

__global__ __launch_bounds__(256) void mma_gemm_dual(
    const __half* A0h, const __half* B0h,
    const __half* A1h, const __half* B1h,
    const float* bias, float* C)
{
    GSrc s0{A0h, B0h};
    GSrc s1{A1h, B1h};
    mma_core(s0, s1, 64, bias, C, blockIdx.y * 128, blockIdx.x * 128);
}

// ---------------------------------------------------------------------------
// fp32 -> fp16 convert, vectorized
// ---------------------------------------------------------------------------
__global__ __launch_bounds__(256) void cvt_half(
    const float4* __restrict__ X, __half* __restrict__ H)
{
    size_t idx = (size_t)blockIdx.x * 256 + threadIdx.x;
    float4 v = X[idx];
    __half h[4];
    h[0] = __float2half(v.x);
    h[1] = __float2half(v.y);
    h[2] = __float2half(v.z);
    h[3] = __float2half(v.w);
    *(uint2*)(H + idx * 4) = *(uint2*)h;
}

// ---------------------------------------------------------------------------
// Weight transpose + fp16 convert (z-batched): W[K,N] fp32 -> Th [N,K] fp16
// ---------------------------------------------------------------------------
struct WtPtrs {
    const float* W[6];
    __half* Th[6];
    int n;
};

__device__ __forceinline__ void wt_cvt_body(
    const float* __restrict__ W, __half* __restrict__ Th)
{
    __shared__ float t[32][33];
    int tx = threadIdx.x, ty = threadIdx.y;
    int n0 = blockIdx.x * 32, k0 = blockIdx.y * 32;
#pragma unroll
    for (int j = 0; j < 4; ++j) {
        int k = k0 + ty + j * 8;
        t[ty + j * 8][tx] = W[(size_t)k * DD + n0 + tx];
    }
    __syncthreads();
#pragma unroll
    for (int j = 0; j < 4; ++j) {
        int n = n0 + ty + j * 8;
        int k = k0 + tx;
        Th[(size_t)n * DD + k] = __float2half(t[tx][ty + j * 8]);
    }
}

__global__ void wt_cvt_batch(WtPtrs p)
{
    wt_cvt_body(p.W[blockIdx.z], p.Th[blockIdx.z]);
}

// ---------------------------------------------------------------------------
// Scalar fp32 GEMM body (fixed 1024x1024x1024, no bias) + z=2 fold kernel
// ---------------------------------------------------------------------------
__device__ __forceinline__ void gemm_scalar_body(
    const float* __restrict__ A, const float* __restrict__ B,
    float* __restrict__ C)
{
    __shared__ float As[16][128];
    __shared__ float Bs[16][128];
    const int tid = threadIdx.x;
    const int bm = blockIdx.y * 128;
    const int bn = blockIdx.x * 128;
    const int tm = (tid >> 4) << 3;
    const int tn = (tid & 15) << 3;

    unsigned long long acc2[8][4];
#pragma unroll
    for (int i = 0; i < 8; ++i)
#pragma unroll
        for (int j = 0; j < 4; ++j) acc2[i][j] = 0ull;

    const int nk = DD >> 4;
    float4 aR[2], bR[2];
    auto loadTile = [&](int kt) {
        const int k0 = kt << 4;
#pragma unroll
        for (int j = 0; j < 2; ++j) {
            int i = tid + (j << 8);
            int ar = i >> 2, ac = (i & 3) << 2;
            aR[j] = *(const float4*)(A + (size_t)(bm + ar) * DD + k0 + ac);
            int br = i >> 5, bc = (i & 31) << 2;
            bR[j] = *(const float4*)(B + (size_t)(k0 + br) * DD + bn + bc);
        }
    };
    auto storeTile = [&]() {
#pragma unroll
        for (int j = 0; j < 2; ++j) {
            int i = tid + (j << 8);
            int ar = i >> 2, ac = (i & 3) << 2;
            As[ac + 0][ar] = aR[j].x;
            As[ac + 1][ar] = aR[j].y;
            As[ac + 2][ar] = aR[j].z;
            As[ac + 3][ar] = aR[j].w;
            int br = i >> 5, bc = (i & 31) << 2;
            *(float4*)&Bs[br][bc] = bR[j];
        }
    };
    loadTile(0);
    storeTile();
    __syncthreads();
    for (int kt = 0; kt < nk; ++kt) {
        if (kt + 1 < nk) loadTile(kt + 1);
#pragma unroll
        for (int k = 0; k < 16; ++k) {
            float4 a0 = *(const float4*)&As[k][tm];
            float4 a1 = *(const float4*)&As[k][tm + 4];
            float4 b0 = *(const float4*)&Bs[k][tn];
            float4 b1 = *(const float4*)&Bs[k][tn + 4];
            unsigned long long rbp[4] = {pk2(b0.x, b0.y), pk2(b0.z, b0.w),
                                         pk2(b1.x, b1.y), pk2(b1.z, b1.w)};
            float ra[8] = {a0.x, a0.y, a0.z, a0.w, a1.x, a1.y, a1.z, a1.w};
#pragma unroll
            for (int i = 0; i < 8; ++i) {
                unsigned long long aa = pk2(ra[i], ra[i]);
#pragma unroll
                for (int jp = 0; jp < 4; ++jp) fma2(acc2[i][jp], aa, rbp[jp]);
            }
        }
        __syncthreads();
        if (kt + 1 < nk) {
            storeTile();
            __syncthreads();
        }
    }
#pragma unroll
    for (int i = 0; i < 8; ++i) {
        float* crow = C + (size_t)(bm + tm + i) * DD + bn + tn;
#pragma unroll
        for (int jp = 0; jp < 4; ++jp) {
            float2 f = upk(acc2[i][jp]);
            *(float2*)(crow + 2 * jp) = f;
        }
    }
}

__global__ __launch_bounds__(256) void fold2_kernel(
    const float* __restrict__ sa_o_w, const float* __restrict__ ta_o_w,
    const float* __restrict__ fuse_w, float* __restrict__ W1,
    float* __restrict__ W2)
{
    if (blockIdx.z == 0)
        gemm_scalar_body(sa_o_w, fuse_w, W1);
    else
        gemm_scalar_body(ta_o_w, fuse_w + (size_t)DD * DD, W2);
}

// ---------------------------------------------------------------------------
// Merged attention: blocks [0,2048) temporal, [2048,4096) spatial.
// fp32 q/k/v in, fp16 out. (R9-verified)
// ---------------------------------------------------------------------------
__device__ __forceinline__ void temporal_body(
    const float* __restrict__ Q, const float* __restrict__ Kp,
    const float* __restrict__ Vp, const int* __restrict__ mask,
    __half* __restrict__ O, int gid)
{
    __shared__ float Ks[64][64];
    __shared__ float Vs[64][64];
    __shared__ int Msk[64];

    int h = gid & 15;
    int clip = (gid >> 4) & 7;
    int b = gid >> 7;
    const size_t base = ((size_t)b * SS + clip) * DD + h * DK;
    const int RS = CLIPC * DD;

    int cq = threadIdx.x;
    unsigned long long qv[32];
    {
        const unsigned long long* qp =
            (const unsigned long long*)(Q + base + (size_t)cq * RS);
#pragma unroll
        for (int i = 0; i < 32; ++i) qv[i] = qp[i];
    }
    unsigned long long acc[32];
#pragma unroll
    for (int i = 0; i < 32; ++i) acc[i] = 0ull;
    float mmax = -1e30f, l = 0.f;

    const int lr = threadIdx.x >> 2;
    const int lc = (threadIdx.x & 3) << 4;

    for (int kt = 0; kt < 4; ++kt) {
        __syncthreads();
        {
            const float* krow = Kp + base + (size_t)(kt * 64 + lr) * RS;
            const float* vrow = Vp + base + (size_t)(kt * 64 + lr) * RS;
#pragma unroll
            for (int j = 0; j < 4; ++j) {
                *(float4*)&Ks[lr][lc + 4 * j] = *(const float4*)(krow + lc + 4 * j);
                *(float4*)&Vs[lr][lc + 4 * j] = *(const float4*)(vrow + lc + 4 * j);
            }
            if (threadIdx.x < 64)
                Msk[threadIdx.x] =
                    mask[(size_t)b * SS + (size_t)(kt * 64 + threadIdx.x) * CLIPC + clip];
        }
        __syncthreads();

        for (int kk = 0; kk < 64; ++kk) {
            if (Msk[kk] == 0) continue;
            const unsigned long long* kr = (const unsigned long long*)&Ks[kk][0];
            unsigned long long d2 = 0ull;
#pragma unroll
            for (int i = 0; i < 32; ++i) fma2(d2, qv[i], kr[i]);
            float2 dd = upk(d2);
            float s = (dd.x + dd.y) * 0.125f;
            if (s > mmax) {
                float corr = __expf(mmax - s);
                unsigned long long cc = pk2(corr, corr);
#pragma unroll
                for (int i = 0; i < 32; ++i) mul2(acc[i], cc);
                l *= corr;
                mmax = s;
            }
            float p = __expf(s - mmax);
            l += p;
            unsigned long long pp = pk2(p, p);
            const unsigned long long* vr = (const unsigned long long*)&Vs[kk][0];
#pragma unroll
            for (int i = 0; i < 32; ++i) fma2(acc[i], pp, vr[i]);
        }
    }
    float inv = 1.0f / l;
    __half2* op = (__half2*)(O + base + (size_t)cq * RS);
#pragma unroll
    for (int i = 0; i < 32; ++i) {
        float2 f = upk(acc[i]);
        op[i] = __floats2half2_rn(f.x * inv, f.y * inv);
    }
}

__device__ __forceinline__ void spatial_body(
    const float* __restrict__ Q, const float* __restrict__ Kp,
    const float* __restrict__ Vp, const int* __restrict__ mask,
    __half* __restrict__ O, int blk)
{
    int unit = blk * 2 + (threadIdx.x >> 7);
    int t = threadIdx.x & 127;
    int h = t >> 3, qi = t & 7;
    int b = unit >> 8, nc = unit & 255;
    size_t rowBase = (size_t)b * SS + (size_t)nc * CLIPC;

    unsigned long long qv[32];
    {
        const unsigned long long* qp =
            (const unsigned long long*)(Q + (rowBase + qi) * DD + h * DK);
#pragma unroll
        for (int i = 0; i < 32; ++i) qv[i] = qp[i];
    }
    const float* kbase = Kp + rowBase * DD + h * DK;
    float sc[8];
    float mx = -1e30f;
#pragma unroll
    for (int kk = 0; kk < 8; ++kk) {
        const unsigned long long* kr =
            (const unsigned long long*)(kbase + (size_t)kk * DD);
        unsigned long long d2 = 0ull;
#pragma unroll
        for (int i = 0; i < 32; ++i) fma2(d2, qv[i], kr[i]);
        float2 dd = upk(d2);
        float s = (dd.x + dd.y) * 0.125f;
        sc[kk] = (mask[rowBase + kk] != 0) ? s : -1e30f;
        mx = fmaxf(mx, sc[kk]);
    }
    float p[8], sum = 0.f;
#pragma unroll
    for (int kk = 0; kk < 8; ++kk) {
        p[kk] = __expf(sc[kk] - mx);
        sum += p[kk];
    }
    float inv = 1.0f / sum;
    unsigned long long acc[32];
#pragma unroll
    for (int i = 0; i < 32; ++i) acc[i] = 0ull;
    const float* vbase = Vp + rowBase * DD + h * DK;
#pragma unroll
    for (int kk = 0; kk < 8; ++kk) {
        unsigned long long pp = pk2(p[kk], p[kk]);
        const unsigned long long* vr =
            (const unsigned long long*)(vbase + (size_t)kk * DD);
#pragma unroll
        for (int i = 0; i < 32; ++i) fma2(acc[i], pp, vr[i]);
    }
    __half2* op = (__half2*)(O + (rowBase + qi) * DD + h * DK);
#pragma unroll
    for (int i = 0; i < 32; ++i) {
        float2 f = upk(acc[i]);
        op[i] = __floats2half2_rn(f.x * inv, f.y * inv);
    }
}

__global__ __launch_bounds__(256) void attn_merged(
    const float* __restrict__ qs, const float* __restrict__ ks,
    const float* __restrict__ vs, const float* __restrict__ qt,
    const float* __restrict__ kt, const float* __restrict__ vt,
    const int* __restrict__ mask, __half* __restrict__ csh,
    __half* __restrict__ cth)
{
    int blk = blockIdx.x;
    if (blk < BB * CLIPC * HH) {
        temporal_body(qt, kt, vt, mask, cth, blk);  // long blocks first
    } else {
        spatial_body(qs, ks, vs, mask, csh, blk - BB * CLIPC * HH);
    }
}

// ---------------------------------------------------------------------------
// bias combine, parallel 2-stage
// ---------------------------------------------------------------------------
__global__ void bias_partial(const float* __restrict__ sab,
                             const float* __restrict__ tab,
                             const float* __restrict__ fw,
                             float* __restrict__ part)
{
    int n = blockIdx.x * 256 + threadIdx.x;
    int j = blockIdx.y;
    int k0 = j * 64;
    float s = 0.f;
#pragma unroll 8
    for (int k = k0; k < k0 + 64; ++k) {
        float coef = (k < DD) ? sab[k] : tab[k - DD];
        s += coef * fw[(size_t)k * DD + n];
    }
    part[(size_t)j * DD + n] = s;
}

__global__ void bias_reduce(const float* __restrict__ part,
                            const float* __restrict__ fb,
                            float* __restrict__ bc)
{
    int n = blockIdx.x * 256 + threadIdx.x;
    float s = fb[n];
#pragma unroll
    for (int j = 0; j < 32; ++j) s += part[(size_t)j * DD + n];
    bc[n] = s;
}

// ---------------------------------------------------------------------------
// Launch sequence (sequential, R9 structure; fork removed — measured neutral)
// ---------------------------------------------------------------------------
extern "C" void kernel_launch(void* const* d_in, const int* in_sizes, int n_in,
                              void* d_out, int out_size)
{
    const float* x       = (const float*)d_in[0];
    const int*   mask    = (const int*)d_in[1];
    const float* sa_q_w  = (const float*)d_in[2];
    const float* sa_q_b  = (const float*)d_in[3];
    const float* sa_k_w  = (const float*)d_in[4];
    const float* sa_k_b  = (const float*)d_in[5];
    const float* sa_v_w  = (const float*)d_in[6];
    const float* sa_v_b  = (const float*)d_in[7];
    const float* sa_o_w  = (const float*)d_in[8];
    const float* sa_o_b  = (const float*)d_in[9];
    const float* ta_q_w  = (const float*)d_in[10];
    const float* ta_q_b  = (const float*)d_in[11];
    const float* ta_k_w  = (const float*)d_in[12];
    const float* ta_k_b  = (const float*)d_in[13];
    const float* ta_v_w  = (const float*)d_in[14];
    const float* ta_v_b  = (const float*)d_in[15];
    const float* ta_o_w  = (const float*)d_in[16];
    const float* ta_o_b  = (const float*)d_in[17];
    const float* fuse_w  = (const float*)d_in[18];
    const float* fuse_b  = (const float*)d_in[19];
    float* out = (float*)d_out;

    float *qs, *ks, *vs, *qt, *kt, *vt, *W1, *W2, *bc, *bcp;
    cudaGetSymbolAddress((void**)&qs, g_qs);
    cudaGetSymbolAddress((void**)&ks, g_ks);
    cudaGetSymbolAddress((void**)&vs, g_vs);
    cudaGetSymbolAddress((void**)&qt, g_qt);
    cudaGetSymbolAddress((void**)&kt, g_kt);
    cudaGetSymbolAddress((void**)&vt, g_vt);
    cudaGetSymbolAddress((void**)&W1, g_W1);
    cudaGetSymbolAddress((void**)&W2, g_W2);
    cudaGetSymbolAddress((void**)&bc, g_bc);
    cudaGetSymbolAddress((void**)&bcp, g_bcp);

    __half *xh, *csh, *cth, *wth;
    cudaGetSymbolAddress((void**)&xh, g_xh);
    cudaGetSymbolAddress((void**)&csh, g_csh);
    cudaGetSymbolAddress((void**)&cth, g_cth);
    cudaGetSymbolAddress((void**)&wth, g_wth);
    const size_t WSZ = (size_t)DD * DD;

    cudaFuncSetAttribute(mma_gemm_qkv, cudaFuncAttributeMaxDynamicSharedMemorySize,
                         SMEM_DYN);
    cudaFuncSetAttribute(mma_gemm_dual, cudaFuncAttributeMaxDynamicSharedMemorySize,
                         SMEM_DYN);

    const int nBlkCvt = MROWS * DD / 4 / 256;  // 32768
    dim3 bT(32, 8);

    // 0) convert x to fp16
    cvt_half<<<nBlkCvt, 256>>>((const float4*)x, xh);

    // 1) transpose + convert the six QKV weights (z-batched)
    {
        WtPtrs wp;
        const float* ws[6] = {sa_q_w, sa_k_w, sa_v_w, ta_q_w, ta_k_w, ta_v_w};
        for (int i = 0; i < 6; ++i) {
            wp.W[i] = ws[i];
            wp.Th[i] = wth + i * WSZ;
        }
        wp.n = 6;
        wt_cvt_batch<<<dim3(32, 32, 6), bT>>>(wp);
    }

    // 2) fold o-proj into fuse: W1 = sa_o_w@fuse_top, W2 = ta_o_w@fuse_bot (z=2)
    fold2_kernel<<<dim3(8, 8, 2), 256>>>(sa_o_w, ta_o_w, fuse_w, W1, W2);

    // 3,4) combined bias
    bias_partial<<<dim3(4, 32), 256>>>(sa_o_b, ta_o_b, fuse_w, bcp);
    bias_reduce<<<4, 256>>>(bcp, fuse_b, bc);

    // 5) six QKV projections on tensor cores (1-pass fp16)
    QkvPtrs qp;
    float* outs[6] = {qs, ks, vs, qt, kt, vt};
    const float* biases[6] = {sa_q_b, sa_k_b, sa_v_b, ta_q_b, ta_k_b, ta_v_b};
    for (int i = 0; i < 6; ++i) {
        qp.Bh[i] = wth + i * WSZ;
        qp.bias[i] = biases[i];
        qp.C[i] = outs[i];
    }
    mma_gemm_qkv<<<dim3(DD / 128, MROWS / 128, 6), 256, SMEM_DYN>>>(xh, qp);

    // 6) transpose + convert folded W1/W2 (z-batched)
    {
        WtPtrs wp;
        wp.W[0] = W1; wp.Th[0] = wth + 6 * WSZ;
        wp.W[1] = W2; wp.Th[1] = wth + 7 * WSZ;
        wp.n = 2;
        wt_cvt_batch<<<dim3(32, 32, 2), bT>>>(wp);
    }

    // 7) merged attention (temporal first, spatial backfills)
    attn_merged<<<BB * CLIPC * HH + BB * NCC / 2, 256>>>(
        qs, ks, vs, qt, kt, vt, mask, csh, cth);

    // 8) fused output: out = cs@W1t + ct@W2t + bc (single dual-K tensor GEMM)
    mma_gemm_dual<<<dim3(DD / 128, MROWS / 128), 256, SMEM_DYN>>>(
        csh, wth + 6 * WSZ, cth, wth + 7 * WSZ, bc, out);
}

// round 13
// speedup vs baseline: 2.1092x; 1.0063x over previous
#include <cuda_runtime.h>
#include <cuda_fp16.h>
#include <cstdint>

// Problem constants
#define BB 16
#define SS 2048
#define DD 1024
#define HH 16
#define DK 64
#define CLIPC 8
#define NCC 256
#define MROWS (BB * SS)  // 32768

// ---------------------------------------------------------------------------
// Scratch (static __device__ arrays; no allocation allowed)
// ---------------------------------------------------------------------------
__device__ float g_qs[MROWS * DD];
__device__ float g_ks[MROWS * DD];
__device__ float g_vs[MROWS * DD];
__device__ float g_qt[MROWS * DD];
__device__ float g_kt[MROWS * DD];
__device__ float g_vt[MROWS * DD];
__device__ float g_W1[DD * DD];
__device__ float g_W2[DD * DD];
__device__ float g_bc[DD];
__device__ float g_bcp[32][DD];

// fp16 buffers
__device__ __half g_xh[MROWS * DD];
__device__ __half g_csh[MROWS * DD];   // spatial attention out (fp16, direct)
__device__ __half g_cth[MROWS * DD];   // temporal attention out (fp16, direct)
// transposed fp16 weights: 0..5 = sa_q,sa_k,sa_v,ta_q,ta_k,ta_v; 6=W1; 7=W2
__device__ __half g_wth[8][DD * DD];

// ---------------------------------------------------------------------------
// Packed f32x2 helpers
// ---------------------------------------------------------------------------
__device__ __forceinline__ unsigned long long pk2(float lo, float hi) {
    unsigned long long r;
    asm("mov.b64 %0, {%1, %2};" : "=l"(r) : "f"(lo), "f"(hi));
    return r;
}
__device__ __forceinline__ void fma2(unsigned long long& d, unsigned long long a,
                                     unsigned long long b) {
    asm("fma.rn.f32x2 %0, %1, %2, %0;" : "+l"(d) : "l"(a), "l"(b));
}
__device__ __forceinline__ void mul2(unsigned long long& d, unsigned long long a) {
    asm("mul.rn.f32x2 %0, %0, %1;" : "+l"(d) : "l"(a));
}
__device__ __forceinline__ float2 upk(unsigned long long v) {
    float2 f;
    asm("mov.b64 {%0, %1}, %2;" : "=f"(f.x), "=f"(f.y) : "l"(v));
    return f;
}

// ---------------------------------------------------------------------------
// mma.sync helpers (base PTX ISA — compiles at .target sm_103)
// ---------------------------------------------------------------------------
__device__ __forceinline__ uint32_t smem_u32(const void* p) {
    uint32_t a;
    asm("{ .reg .u64 t; cvta.to.shared.u64 t, %1; cvt.u32.u64 %0, t; }"
        : "=r"(a) : "l"(p));
    return a;
}
__device__ __forceinline__ void ldsm4(uint32_t* r, uint32_t addr) {
    asm volatile(
        "ldmatrix.sync.aligned.m8n8.x4.shared.b16 {%0,%1,%2,%3}, [%4];"
        : "=r"(r[0]), "=r"(r[1]), "=r"(r[2]), "=r"(r[3]) : "r"(addr));
}
__device__ __forceinline__ void mma16816(float* d, const uint32_t* a,
                                         const uint32_t* b) {
    asm volatile(
        "mma.sync.aligned.m16n8k16.row.col.f32.f16.f16.f32 "
        "{%0,%1,%2,%3}, {%4,%5,%6,%7}, {%8,%9}, {%0,%1,%2,%3};"
        : "+f"(d[0]), "+f"(d[1]), "+f"(d[2]), "+f"(d[3])
        : "r"(a[0]), "r"(a[1]), "r"(a[2]), "r"(a[3]), "r"(b[0]), "r"(b[1]));
}
#define CPASYNC16(dst, src) \
    asm volatile("cp.async.cg.shared.global [%0], [%1], 16;" :: "r"(dst), "l"(src))
#define CPCOMMIT() asm volatile("cp.async.commit_group;" ::: "memory")
#define CPWAIT2() asm volatile("cp.async.wait_group 2;" ::: "memory")

// smem geometry: row pitch 80B (40 fp16), conflict-free for ldmatrix.
#define PITCHB 80
#define TILEB (128 * PITCHB)     // 10240 bytes per operand tile
#define STAGEB (2 * TILEB)       // Ah, Bh (1-pass)
#define NSTAGE 4
#define SMEM_DYN (NSTAGE * STAGEB)  // 81920 bytes

// ---------------------------------------------------------------------------
// fp16 1-pass GEMM core: C = Ah*Bh^T + bias (fp32 accum/output).
// CTA tile 128x128, BK=32, 8 warps (4M x 2N — R4-proven layout).
// 4-stage cp.async, SINGLE __syncthreads per chunk:
//   wait(kc resident) -> sync (kc-1 fully consumed) -> refill slot (kc-1)%4
//   -> compute kc.   (isolated A/B vs R12's 3-stage/2-sync)
// ---------------------------------------------------------------------------
struct GSrc {
    const __half *Ah, *Bh;
};

__device__ __forceinline__ void mma_core(
    GSrc s0, GSrc s1, int nchunk,
    const float* __restrict__ bias, float* __restrict__ C, int bm, int bn)
{
    extern __shared__ char sm[];
    const uint32_t sbase = smem_u32(sm);
    const int tid = threadIdx.x, wid = tid >> 5, l = tid & 31;
    const int wm = (wid & 3) * 32;   // warp row offset in CTA tile
    const int wn = (wid >> 2) * 64;  // warp col offset

    // stage copy: 2 tiles x 512 16B-chunks, 2 chunks per thread per tile
    auto issue = [&](int kc) {
        if (kc < nchunk) {
            const GSrc& s = (kc < 32) ? s0 : s1;
            const int kl = kc & 31;
            const uint32_t st = sbase + (kc % NSTAGE) * STAGEB;
            const __half* srcs[2] = {s.Ah, s.Bh};
#pragma unroll
            for (int t2 = 0; t2 < 2; ++t2) {
                const int rb = (t2 == 0) ? bm : bn;
                const uint32_t doff = st + t2 * TILEB;
                const __half* sp = srcs[t2];
#pragma unroll
                for (int j = 0; j < 2; ++j) {
                    int c = tid + j * 256;
                    int row = c >> 2, pos = c & 3;
                    uint32_t dst = doff + row * PITCHB + pos * 16;
                    const void* src = sp + (size_t)(rb + row) * DD + kl * 32 + pos * 8;
                    CPASYNC16(dst, src);
                }
            }
        }
        CPCOMMIT();
    };

    issue(0);
    issue(1);
    issue(2);

    float acc[2][8][4];
#pragma unroll
    for (int mi = 0; mi < 2; ++mi)
#pragma unroll
        for (int ni = 0; ni < 8; ++ni)
#pragma unroll
            for (int f = 0; f < 4; ++f) acc[mi][ni][f] = 0.0f;

    const uint32_t m8 = l >> 3;
    const uint32_t laneArow = (m8 & 1) * 8 + (l & 7);
    const uint32_t laneAkb = (m8 >> 1) * 16;
    const uint32_t laneBrow = (m8 >> 1) * 8 + (l & 7);
    const uint32_t laneBkb = (m8 & 1) * 16;

    for (int kc = 0; kc < nchunk; ++kc) {
        CPWAIT2();            // stage kc resident (2 groups still in flight)
        __syncthreads();      // all warps done with stage kc-1
        issue(kc + NSTAGE - 1);  // refill slot (kc-1)%4 — freed by the sync
        const uint32_t st = sbase + (kc % NSTAGE) * STAGEB;
#pragma unroll
        for (int ks = 0; ks < 2; ++ks) {
            const uint32_t kbyte = ks * 32;
            uint32_t ah[2][4];
#pragma unroll
            for (int mi = 0; mi < 2; ++mi) {
                uint32_t r = wm + mi * 16 + laneArow;
                ldsm4(ah[mi], st + 0 * TILEB + r * PITCHB + kbyte + laneAkb);
            }
            uint32_t bh[8][2];
#pragma unroll
            for (int bi = 0; bi < 4; ++bi) {
                uint32_t r = wn + bi * 16 + laneBrow;
                uint32_t q[4];
                ldsm4(q, st + 1 * TILEB + r * PITCHB + kbyte + laneBkb);
                bh[bi * 2][0] = q[0]; bh[bi * 2][1] = q[1];
                bh[bi * 2 + 1][0] = q[2]; bh[bi * 2 + 1][1] = q[3];
            }
#pragma unroll
            for (int mi = 0; mi < 2; ++mi)
#pragma unroll
                for (int ni = 0; ni < 8; ++ni)
                    mma16816(acc[mi][ni], ah[mi], bh[ni]);
        }
    }

    // epilogue
#pragma unroll
    for (int mi = 0; mi < 2; ++mi) {
        const int r0 = bm + wm + mi * 16 + (l >> 2);
#pragma unroll
        for (int ni = 0; ni < 8; ++ni) {
            const int c = bn + wn + ni * 8 + (l & 3) * 2;
            const float b0v = bias[c], b1v = bias[c + 1];
            float2 v0, v1;
            v0.x = acc[mi][ni][0] + b0v;
            v0.y = acc[mi][ni][1] + b1v;
            v1.x = acc[mi][ni][2] + b0v;
            v1.y = acc[mi][ni][3] + b1v;
            *(float2*)(C + (size_t)r0 * DD + c) = v0;
            *(float2*)(C + (size_t)(r0 + 8) * DD + c) = v1;
        }
    }
}

// batched QKV: z selects weight/bias/output; A = x (shared)
struct QkvPtrs {
    const __half* Bh[6];
    const float* bias[6];
    float* C[6];
};

__global__ __launch_bounds__(256) void mma_gemm_qkv(
    const __half* __restrict__ Ah, QkvPtrs p)
{
    int z = blockIdx.z;
    GSrc s{Ah, p.Bh[z]};
    mma_core(s, s, 32, p.bias[z], p.C[z], blockIdx.y * 128, blockIdx.x * 128);
}

__global__ __launch_bounds__(256) void mma_gemm_dual(
    const __half* A0h, const __half* B0h,
    const __half* A1h, const __half* B1h,
    const float* bias, float* C)
{
    GSrc s0{A0h, B0h};
    GSrc s1{A1h, B1h};
    mma_core(s0, s1, 64, bias, C, blockIdx.y * 128, blockIdx.x * 128);
}

// ---------------------------------------------------------------------------
// fp32 -> fp16 convert, vectorized
// ---------------------------------------------------------------------------
__global__ __launch_bounds__(256) void cvt_half(
    const float4* __restrict__ X, __half* __restrict__ H)
{
    size_t idx = (size_t)blockIdx.x * 256 + threadIdx.x;
    float4 v = X[idx];
    __half h[4];
    h[0] = __float2half(v.x);
    h[1] = __float2half(v.y);
    h[2] = __float2half(v.z);
    h[3] = __float2half(v.w);
    *(uint2*)(H + idx * 4) = *(uint2*)h;
}

// ---------------------------------------------------------------------------
// Weight transpose + fp16 convert (z-batched): W[K,N] fp32 -> Th [N,K] fp16
// ---------------------------------------------------------------------------
struct WtPtrs {
    const float* W[6];
    __half* Th[6];
    int n;
};

__device__ __forceinline__ void wt_cvt_body(
    const float* __restrict__ W, __half* __restrict__ Th)
{
    __shared__ float t[32][33];
    int tx = threadIdx.x, ty = threadIdx.y;
    int n0 = blockIdx.x * 32, k0 = blockIdx.y * 32;
#pragma unroll
    for (int j = 0; j < 4; ++j) {
        int k = k0 + ty + j * 8;
        t[ty + j * 8][tx] = W[(size_t)k * DD + n0 + tx];
    }
    __syncthreads();
#pragma unroll
    for (int j = 0; j < 4; ++j) {
        int n = n0 + ty + j * 8;
        int k = k0 + tx;
        Th[(size_t)n * DD + k] = __float2half(t[tx][ty + j * 8]);
    }
}

__global__ void wt_cvt_batch(WtPtrs p)
{
    wt_cvt_body(p.W[blockIdx.z], p.Th[blockIdx.z]);
}

// ---------------------------------------------------------------------------
// Scalar fp32 GEMM body (fixed 1024x1024x1024, no bias) + z=2 fold kernel
// ---------------------------------------------------------------------------
__device__ __forceinline__ void gemm_scalar_body(
    const float* __restrict__ A, const float* __restrict__ B,
    float* __restrict__ C)
{
    __shared__ float As[16][128];
    __shared__ float Bs[16][128];
    const int tid = threadIdx.x;
    const int bm = blockIdx.y * 128;
    const int bn = blockIdx.x * 128;
    const int tm = (tid >> 4) << 3;
    const int tn = (tid & 15) << 3;

    unsigned long long acc2[8][4];
#pragma unroll
    for (int i = 0; i < 8; ++i)
#pragma unroll
        for (int j = 0; j < 4; ++j) acc2[i][j] = 0ull;

    const int nk = DD >> 4;
    float4 aR[2], bR[2];
    auto loadTile = [&](int kt) {
        const int k0 = kt << 4;
#pragma unroll
        for (int j = 0; j < 2; ++j) {
            int i = tid + (j << 8);
            int ar = i >> 2, ac = (i & 3) << 2;
            aR[j] = *(const float4*)(A + (size_t)(bm + ar) * DD + k0 + ac);
            int br = i >> 5, bc = (i & 31) << 2;
            bR[j] = *(const float4*)(B + (size_t)(k0 + br) * DD + bn + bc);
        }
    };
    auto storeTile = [&]() {
#pragma unroll
        for (int j = 0; j < 2; ++j) {
            int i = tid + (j << 8);
            int ar = i >> 2, ac = (i & 3) << 2;
            As[ac + 0][ar] = aR[j].x;
            As[ac + 1][ar] = aR[j].y;
            As[ac + 2][ar] = aR[j].z;
            As[ac + 3][ar] = aR[j].w;
            int br = i >> 5, bc = (i & 31) << 2;
            *(float4*)&Bs[br][bc] = bR[j];
        }
    };
    loadTile(0);
    storeTile();
    __syncthreads();
    for (int kt = 0; kt < nk; ++kt) {
        if (kt + 1 < nk) loadTile(kt + 1);
#pragma unroll
        for (int k = 0; k < 16; ++k) {
            float4 a0 = *(const float4*)&As[k][tm];
            float4 a1 = *(const float4*)&As[k][tm + 4];
            float4 b0 = *(const float4*)&Bs[k][tn];
            float4 b1 = *(const float4*)&Bs[k][tn + 4];
            unsigned long long rbp[4] = {pk2(b0.x, b0.y), pk2(b0.z, b0.w),
                                         pk2(b1.x, b1.y), pk2(b1.z, b1.w)};
            float ra[8] = {a0.x, a0.y, a0.z, a0.w, a1.x, a1.y, a1.z, a1.w};
#pragma unroll
            for (int i = 0; i < 8; ++i) {
                unsigned long long aa = pk2(ra[i], ra[i]);
#pragma unroll
                for (int jp = 0; jp < 4; ++jp) fma2(acc2[i][jp], aa, rbp[jp]);
            }
        }
        __syncthreads();
        if (kt + 1 < nk) {
            storeTile();
            __syncthreads();
        }
    }
#pragma unroll
    for (int i = 0; i < 8; ++i) {
        float* crow = C + (size_t)(bm + tm + i) * DD + bn + tn;
#pragma unroll
        for (int jp = 0; jp < 4; ++jp) {
            float2 f = upk(acc2[i][jp]);
            *(float2*)(crow + 2 * jp) = f;
        }
    }
}

__global__ __launch_bounds__(256) void fold2_kernel(
    const float* __restrict__ sa_o_w, const float* __restrict__ ta_o_w,
    const float* __restrict__ fuse_w, float* __restrict__ W1,
    float* __restrict__ W2)
{
    if (blockIdx.z == 0)
        gemm_scalar_body(sa_o_w, fuse_w, W1);
    else
        gemm_scalar_body(ta_o_w, fuse_w + (size_t)DD * DD, W2);
}

// ---------------------------------------------------------------------------
// Merged attention: blocks [0,2048) temporal, [2048,4096) spatial.
// fp32 q/k/v in, fp16 out. (R9-verified)
// ---------------------------------------------------------------------------
__device__ __forceinline__ void temporal_body(
    const float* __restrict__ Q, const float* __restrict__ Kp,
    const float* __restrict__ Vp, const int* __restrict__ mask,
    __half* __restrict__ O, int gid)
{
    __shared__ float Ks[64][64];
    __shared__ float Vs[64][64];
    __shared__ int Msk[64];

    int h = gid & 15;
    int clip = (gid >> 4) & 7;
    int b = gid >> 7;
    const size_t base = ((size_t)b * SS + clip) * DD + h * DK;
    const int RS = CLIPC * DD;

    int cq = threadIdx.x;
    unsigned long long qv[32];
    {
        const unsigned long long* qp =
            (const unsigned long long*)(Q + base + (size_t)cq * RS);
#pragma unroll
        for (int i = 0; i < 32; ++i) qv[i] = qp[i];
    }
    unsigned long long acc[32];
#pragma unroll
    for (int i = 0; i < 32; ++i) acc[i] = 0ull;
    float mmax = -1e30f, l = 0.f;

    const int lr = threadIdx.x >> 2;
    const int lc = (threadIdx.x & 3) << 4;

    for (int kt = 0; kt < 4; ++kt) {
        __syncthreads();
        {
            const float* krow = Kp + base + (size_t)(kt * 64 + lr) * RS;
            const float* vrow = Vp + base + (size_t)(kt * 64 + lr) * RS;
#pragma unroll
            for (int j = 0; j < 4; ++j) {
                *(float4*)&Ks[lr][lc + 4 * j] = *(const float4*)(krow + lc + 4 * j);
                *(float4*)&Vs[lr][lc + 4 * j] = *(const float4*)(vrow + lc + 4 * j);
            }
            if (threadIdx.x < 64)
                Msk[threadIdx.x] =
                    mask[(size_t)b * SS + (size_t)(kt * 64 + threadIdx.x) * CLIPC + clip];
        }
        __syncthreads();

        for (int kk = 0; kk < 64; ++kk) {
            if (Msk[kk] == 0) continue;
            const unsigned long long* kr = (const unsigned long long*)&Ks[kk][0];
            unsigned long long d2 = 0ull;
#pragma unroll
            for (int i = 0; i < 32; ++i) fma2(d2, qv[i], kr[i]);
            float2 dd = upk(d2);
            float s = (dd.x + dd.y) * 0.125f;
            if (s > mmax) {
                float corr = __expf(mmax - s);
                unsigned long long cc = pk2(corr, corr);
#pragma unroll
                for (int i = 0; i < 32; ++i) mul2(acc[i], cc);
                l *= corr;
                mmax = s;
            }
            float p = __expf(s - mmax);
            l += p;
            unsigned long long pp = pk2(p, p);
            const unsigned long long* vr = (const unsigned long long*)&Vs[kk][0];
#pragma unroll
            for (int i = 0; i < 32; ++i) fma2(acc[i], pp, vr[i]);
        }
    }
    float inv = 1.0f / l;
    __half2* op = (__half2*)(O + base + (size_t)cq * RS);
#pragma unroll
    for (int i = 0; i < 32; ++i) {
        float2 f = upk(acc[i]);
        op[i] = __floats2half2_rn(f.x * inv, f.y * inv);
    }
}

__device__ __forceinline__ void spatial_body(
    const float* __restrict__ Q, const float* __restrict__ Kp,
    const float* __restrict__ Vp, const int* __restrict__ mask,
    __half* __restrict__ O, int blk)
{
    int unit = blk * 2 + (threadIdx.x >> 7);
    int t = threadIdx.x & 127;
    int h = t >> 3, qi = t & 7;
    int b = unit >> 8, nc = unit & 255;
    size_t rowBase = (size_t)b * SS + (size_t)nc * CLIPC;

    unsigned long long qv[32];
    {
        const unsigned long long* qp =
            (const unsigned long long*)(Q + (rowBase + qi) * DD + h * DK);
#pragma unroll
        for (int i = 0; i < 32; ++i) qv[i] = qp[i];
    }
    const float* kbase = Kp + rowBase * DD + h * DK;
    float sc[8];
    float mx = -1e30f;
#pragma unroll
    for (int kk = 0; kk < 8; ++kk) {
        const unsigned long long* kr =
            (const unsigned long long*)(kbase + (size_t)kk * DD);
        unsigned long long d2 = 0ull;
#pragma unroll
        for (int i = 0; i < 32; ++i) fma2(d2, qv[i], kr[i]);
        float2 dd = upk(d2);
        float s = (dd.x + dd.y) * 0.125f;
        sc[kk] = (mask[rowBase + kk] != 0) ? s : -1e30f;
        mx = fmaxf(mx, sc[kk]);
    }
    float p[8], sum = 0.f;
#pragma unroll
    for (int kk = 0; kk < 8; ++kk) {
        p[kk] = __expf(sc[kk] - mx);
        sum += p[kk];
    }
    float inv = 1.0f / sum;
    unsigned long long acc[32];
#pragma unroll
    for (int i = 0; i < 32; ++i) acc[i] = 0ull;
    const float* vbase = Vp + rowBase * DD + h * DK;
#pragma unroll
    for (int kk = 0; kk < 8; ++kk) {
        unsigned long long pp = pk2(p[kk], p[kk]);
        const unsigned long long* vr =
            (const unsigned long long*)(vbase + (size_t)kk * DD);
#pragma unroll
        for (int i = 0; i < 32; ++i) fma2(acc[i], pp, vr[i]);
    }
    __half2* op = (__half2*)(O + (rowBase + qi) * DD + h * DK);
#pragma unroll
    for (int i = 0; i < 32; ++i) {
        float2 f = upk(acc[i]);
        op[i] = __floats2half2_rn(f.x * inv, f.y * inv);
    }
}

__global__ __launch_bounds__(256) void attn_merged(
    const float* __restrict__ qs, const float* __restrict__ ks,
    const float* __restrict__ vs, const float* __restrict__ qt,
    const float* __restrict__ kt, const float* __restrict__ vt,
    const int* __restrict__ mask, __half* __restrict__ csh,
    __half* __restrict__ cth)
{
    int blk = blockIdx.x;
    if (blk < BB * CLIPC * HH) {
        temporal_body(qt, kt, vt, mask, cth, blk);  // long blocks first
    } else {
        spatial_body(qs, ks, vs, mask, csh, blk - BB * CLIPC * HH);
    }
}

// ---------------------------------------------------------------------------
// bias combine, parallel 2-stage
// ---------------------------------------------------------------------------
__global__ void bias_partial(const float* __restrict__ sab,
                             const float* __restrict__ tab,
                             const float* __restrict__ fw,
                             float* __restrict__ part)
{
    int n = blockIdx.x * 256 + threadIdx.x;
    int j = blockIdx.y;
    int k0 = j * 64;
    float s = 0.f;
#pragma unroll 8
    for (int k = k0; k < k0 + 64; ++k) {
        float coef = (k < DD) ? sab[k] : tab[k - DD];
        s += coef * fw[(size_t)k * DD + n];
    }
    part[(size_t)j * DD + n] = s;
}

__global__ void bias_reduce(const float* __restrict__ part,
                            const float* __restrict__ fb,
                            float* __restrict__ bc)
{
    int n = blockIdx.x * 256 + threadIdx.x;
    float s = fb[n];
#pragma unroll
    for (int j = 0; j < 32; ++j) s += part[(size_t)j * DD + n];
    bc[n] = s;
}

// ---------------------------------------------------------------------------
// Launch sequence (sequential, R12 structure)
// ---------------------------------------------------------------------------
extern "C" void kernel_launch(void* const* d_in, const int* in_sizes, int n_in,
                              void* d_out, int out_size)
{
    const float* x       = (const float*)d_in[0];
    const int*   mask    = (const int*)d_in[1];
    const float* sa_q_w  = (const float*)d_in[2];
    const float* sa_q_b  = (const float*)d_in[3];
    const float* sa_k_w  = (const float*)d_in[4];
    const float* sa_k_b  = (const float*)d_in[5];
    const float* sa_v_w  = (const float*)d_in[6];
    const float* sa_v_b  = (const float*)d_in[7];
    const float* sa_o_w  = (const float*)d_in[8];
    const float* sa_o_b  = (const float*)d_in[9];
    const float* ta_q_w  = (const float*)d_in[10];
    const float* ta_q_b  = (const float*)d_in[11];
    const float* ta_k_w  = (const float*)d_in[12];
    const float* ta_k_b  = (const float*)d_in[13];
    const float* ta_v_w  = (const float*)d_in[14];
    const float* ta_v_b  = (const float*)d_in[15];
    const float* ta_o_w  = (const float*)d_in[16];
    const float* ta_o_b  = (const float*)d_in[17];
    const float* fuse_w  = (const float*)d_in[18];
    const float* fuse_b  = (const float*)d_in[19];
    float* out = (float*)d_out;

    float *qs, *ks, *vs, *qt, *kt, *vt, *W1, *W2, *bc, *bcp;
    cudaGetSymbolAddress((void**)&qs, g_qs);
    cudaGetSymbolAddress((void**)&ks, g_ks);
    cudaGetSymbolAddress((void**)&vs, g_vs);
    cudaGetSymbolAddress((void**)&qt, g_qt);
    cudaGetSymbolAddress((void**)&kt, g_kt);
    cudaGetSymbolAddress((void**)&vt, g_vt);
    cudaGetSymbolAddress((void**)&W1, g_W1);
    cudaGetSymbolAddress((void**)&W2, g_W2);
    cudaGetSymbolAddress((void**)&bc, g_bc);
    cudaGetSymbolAddress((void**)&bcp, g_bcp);

    __half *xh, *csh, *cth, *wth;
    cudaGetSymbolAddress((void**)&xh, g_xh);
    cudaGetSymbolAddress((void**)&csh, g_csh);
    cudaGetSymbolAddress((void**)&cth, g_cth);
    cudaGetSymbolAddress((void**)&wth, g_wth);
    const size_t WSZ = (size_t)DD * DD;

    cudaFuncSetAttribute(mma_gemm_qkv, cudaFuncAttributeMaxDynamicSharedMemorySize,
                         SMEM_DYN);
    cudaFuncSetAttribute(mma_gemm_dual, cudaFuncAttributeMaxDynamicSharedMemorySize,
                         SMEM_DYN);

    const int nBlkCvt = MROWS * DD / 4 / 256;  // 32768
    dim3 bT(32, 8);

    // 0) convert x to fp16
    cvt_half<<<nBlkCvt, 256>>>((const float4*)x, xh);

    // 1) transpose + convert the six QKV weights (z-batched)
    {
        WtPtrs wp;
        const float* ws[6] = {sa_q_w, sa_k_w, sa_v_w, ta_q_w, ta_k_w, ta_v_w};
        for (int i = 0; i < 6; ++i) {
            wp.W[i] = ws[i];
            wp.Th[i] = wth + i * WSZ;
        }
        wp.n = 6;
        wt_cvt_batch<<<dim3(32, 32, 6), bT>>>(wp);
    }

    // 2) fold o-proj into fuse: W1 = sa_o_w@fuse_top, W2 = ta_o_w@fuse_bot (z=2)
    fold2_kernel<<<dim3(8, 8, 2), 256>>>(sa_o_w, ta_o_w, fuse_w, W1, W2);

    // 3,4) combined bias
    bias_partial<<<dim3(4, 32), 256>>>(sa_o_b, ta_o_b, fuse_w, bcp);
    bias_reduce<<<4, 256>>>(bcp, fuse_b, bc);

    // 5) six QKV projections on tensor cores (1-pass fp16)
    QkvPtrs qp;
    float* outs[6] = {qs, ks, vs, qt, kt, vt};
    const float* biases[6] = {sa_q_b, sa_k_b, sa_v_b, ta_q_b, ta_k_b, ta_v_b};
    for (int i = 0; i < 6; ++i) {
        qp.Bh[i] = wth + i * WSZ;
        qp.bias[i] = biases[i];
        qp.C[i] = outs[i];
    }
    mma_gemm_qkv<<<dim3(DD / 128, MROWS / 128, 6), 256, SMEM_DYN>>>(xh, qp);

    // 6) transpose + convert folded W1/W2 (z-batched)
    {
        WtPtrs wp;
        wp.W[0] = W1; wp.Th[0] = wth + 6 * WSZ;
        wp.W[1] = W2; wp.Th[1] = wth + 7 * WSZ;
        wp.n = 2;
        wt_cvt_batch<<<dim3(32, 32, 2), bT>>>(wp);
    }

    // 7) merged attention (temporal first, spatial backfills)
    attn_merged<<<BB * CLIPC * HH + BB * NCC / 2, 256>>>(
        qs, ks, vs, qt, kt, vt, mask, csh, cth);

    // 8) fused output: out = cs@W1t + ct@W2t + bc (single dual-K tensor GEMM)
    mma_gemm_dual<<<dim3(DD / 128, MROWS / 128), 256, SMEM_DYN>>>(
        csh, wth + 6 * WSZ, cth, wth + 7 * WSZ, bc, out);
}

// round 17
// speedup vs baseline: 2.1680x; 1.0279x over previous
#include <cuda_runtime.h>
#include <cuda_fp16.h>
#include <cstdint>

// Problem constants
#define BB 16
#define SS 2048
#define DD 1024
#define HH 16
#define DK 64
#define CLIPC 8
#define NCC 256
#define MROWS (BB * SS)  // 32768

// ---------------------------------------------------------------------------
// Scratch (static __device__ arrays; no allocation allowed)
// ---------------------------------------------------------------------------
__device__ float g_qs[MROWS * DD];
__device__ float g_ks[MROWS * DD];
__device__ float g_vs[MROWS * DD];
__device__ float g_qt[MROWS * DD];
__device__ float g_kt[MROWS * DD];
__device__ float g_vt[MROWS * DD];
__device__ float g_W1[DD * DD];
__device__ float g_W2[DD * DD];
__device__ float g_bc[DD];
__device__ float g_bcp[32][DD];
__device__ float g_zero[DD];          // zero-initialized (bias for fold GEMM)

// fp16 buffers
__device__ __half g_xh[MROWS * DD];
__device__ __half g_csh[MROWS * DD];   // spatial attention out (fp16, direct)
__device__ __half g_cth[MROWS * DD];   // temporal attention out (fp16, direct)
__device__ __half g_oh[2][DD * DD];    // fp16 of sa_o_w / ta_o_w (A operands)
__device__ __half g_fth[2][DD * DD];   // fp16 transposed fuse halves (B operands)
// transposed fp16 weights: 0..5 = sa_q,sa_k,sa_v,ta_q,ta_k,ta_v; 6=W1; 7=W2
__device__ __half g_wth[8][DD * DD];

// ---------------------------------------------------------------------------
// Packed f32x2 helpers
// ---------------------------------------------------------------------------
__device__ __forceinline__ unsigned long long pk2(float lo, float hi) {
    unsigned long long r;
    asm("mov.b64 %0, {%1, %2};" : "=l"(r) : "f"(lo), "f"(hi));
    return r;
}
__device__ __forceinline__ void fma2(unsigned long long& d, unsigned long long a,
                                     unsigned long long b) {
    asm("fma.rn.f32x2 %0, %1, %2, %0;" : "+l"(d) : "l"(a), "l"(b));
}
__device__ __forceinline__ void mul2(unsigned long long& d, unsigned long long a) {
    asm("mul.rn.f32x2 %0, %0, %1;" : "+l"(d) : "l"(a));
}
__device__ __forceinline__ float2 upk(unsigned long long v) {
    float2 f;
    asm("mov.b64 {%0, %1}, %2;" : "=f"(f.x), "=f"(f.y) : "l"(v));
    return f;
}

// ---------------------------------------------------------------------------
// mma.sync helpers (base PTX ISA — compiles at .target sm_103)
// ---------------------------------------------------------------------------
__device__ __forceinline__ uint32_t smem_u32(const void* p) {
    uint32_t a;
    asm("{ .reg .u64 t; cvta.to.shared.u64 t, %1; cvt.u32.u64 %0, t; }"
        : "=r"(a) : "l"(p));
    return a;
}
__device__ __forceinline__ void ldsm4(uint32_t* r, uint32_t addr) {
    asm volatile(
        "ldmatrix.sync.aligned.m8n8.x4.shared.b16 {%0,%1,%2,%3}, [%4];"
        : "=r"(r[0]), "=r"(r[1]), "=r"(r[2]), "=r"(r[3]) : "r"(addr));
}
__device__ __forceinline__ void mma16816(float* d, const uint32_t* a,
                                         const uint32_t* b) {
    asm volatile(
        "mma.sync.aligned.m16n8k16.row.col.f32.f16.f16.f32 "
        "{%0,%1,%2,%3}, {%4,%5,%6,%7}, {%8,%9}, {%0,%1,%2,%3};"
        : "+f"(d[0]), "+f"(d[1]), "+f"(d[2]), "+f"(d[3])
        : "r"(a[0]), "r"(a[1]), "r"(a[2]), "r"(a[3]), "r"(b[0]), "r"(b[1]));
}
#define CPASYNC16(dst, src) \
    asm volatile("cp.async.cg.shared.global [%0], [%1], 16;" :: "r"(dst), "l"(src))
#define CPCOMMIT() asm volatile("cp.async.commit_group;" ::: "memory")
#define CPWAIT2() asm volatile("cp.async.wait_group 2;" ::: "memory")

// smem geometry: row pitch 80B (40 fp16), conflict-free for ldmatrix.
#define PITCHB 80
#define TILEB (128 * PITCHB)     // 10240 bytes per operand tile
#define STAGEB (2 * TILEB)       // Ah, Bh (1-pass)
#define NSTAGE 4
#define SMEM_DYN (NSTAGE * STAGEB)  // 81920 bytes

// ---------------------------------------------------------------------------
// fp16 1-pass GEMM core: C = Ah*Bh^T + bias (fp32 accum/output).
// CTA tile 128x128, BK=32, 8 warps (4M x 2N). 4-stage, 1 sync/chunk. (R13)
// nchunk = total K / 32.
// ---------------------------------------------------------------------------
struct GSrc {
    const __half *Ah, *Bh;
};

__device__ __forceinline__ void mma_core(
    GSrc s0, GSrc s1, int nchunk,
    const float* __restrict__ bias, float* __restrict__ C, int bm, int bn)
{
    extern __shared__ char sm[];
    const uint32_t sbase = smem_u32(sm);
    const int tid = threadIdx.x, wid = tid >> 5, l = tid & 31;
    const int wm = (wid & 3) * 32;   // warp row offset in CTA tile
    const int wn = (wid >> 2) * 64;  // warp col offset

    auto issue = [&](int kc) {
        if (kc < nchunk) {
            const GSrc& s = (kc < 32) ? s0 : s1;
            const int kl = kc & 31;
            const uint32_t st = sbase + (kc % NSTAGE) * STAGEB;
            const __half* srcs[2] = {s.Ah, s.Bh};
#pragma unroll
            for (int t2 = 0; t2 < 2; ++t2) {
                const int rb = (t2 == 0) ? bm : bn;
                const uint32_t doff = st + t2 * TILEB;
                const __half* sp = srcs[t2];
#pragma unroll
                for (int j = 0; j < 2; ++j) {
                    int c = tid + j * 256;
                    int row = c >> 2, pos = c & 3;
                    uint32_t dst = doff + row * PITCHB + pos * 16;
                    const void* src = sp + (size_t)(rb + row) * DD + kl * 32 + pos * 8;
                    CPASYNC16(dst, src);
                }
            }
        }
        CPCOMMIT();
    };

    issue(0);
    issue(1);
    issue(2);

    float acc[2][8][4];
#pragma unroll
    for (int mi = 0; mi < 2; ++mi)
#pragma unroll
        for (int ni = 0; ni < 8; ++ni)
#pragma unroll
            for (int f = 0; f < 4; ++f) acc[mi][ni][f] = 0.0f;

    const uint32_t m8 = l >> 3;
    const uint32_t laneArow = (m8 & 1) * 8 + (l & 7);
    const uint32_t laneAkb = (m8 >> 1) * 16;
    const uint32_t laneBrow = (m8 >> 1) * 8 + (l & 7);
    const uint32_t laneBkb = (m8 & 1) * 16;

    for (int kc = 0; kc < nchunk; ++kc) {
        CPWAIT2();
        __syncthreads();
        issue(kc + NSTAGE - 1);  // refill slot (kc-1)%4 — freed by the sync
        const uint32_t st = sbase + (kc % NSTAGE) * STAGEB;
#pragma unroll
        for (int ks = 0; ks < 2; ++ks) {
            const uint32_t kbyte = ks * 32;
            uint32_t ah[2][4];
#pragma unroll
            for (int mi = 0; mi < 2; ++mi) {
                uint32_t r = wm + mi * 16 + laneArow;
                ldsm4(ah[mi], st + 0 * TILEB + r * PITCHB + kbyte + laneAkb);
            }
            uint32_t bh[8][2];
#pragma unroll
            for (int bi = 0; bi < 4; ++bi) {
                uint32_t r = wn + bi * 16 + laneBrow;
                uint32_t q[4];
                ldsm4(q, st + 1 * TILEB + r * PITCHB + kbyte + laneBkb);
                bh[bi * 2][0] = q[0]; bh[bi * 2][1] = q[1];
                bh[bi * 2 + 1][0] = q[2]; bh[bi * 2 + 1][1] = q[3];
            }
#pragma unroll
            for (int mi = 0; mi < 2; ++mi)
#pragma unroll
                for (int ni = 0; ni < 8; ++ni)
                    mma16816(acc[mi][ni], ah[mi], bh[ni]);
        }
    }

    // epilogue
#pragma unroll
    for (int mi = 0; mi < 2; ++mi) {
        const int r0 = bm + wm + mi * 16 + (l >> 2);
#pragma unroll
        for (int ni = 0; ni < 8; ++ni) {
            const int c = bn + wn + ni * 8 + (l & 3) * 2;
            const float b0v = bias[c], b1v = bias[c + 1];
            float2 v0, v1;
            v0.x = acc[mi][ni][0] + b0v;
            v0.y = acc[mi][ni][1] + b1v;
            v1.x = acc[mi][ni][2] + b0v;
            v1.y = acc[mi][ni][3] + b1v;
            *(float2*)(C + (size_t)r0 * DD + c) = v0;
            *(float2*)(C + (size_t)(r0 + 8) * DD + c) = v1;
        }
    }
}

// batched QKV: z selects weight/bias/output; A = x (shared)
struct QkvPtrs {
    const __half* Bh[6];
    const float* bias[6];
    float* C[6];
};

__global__ __launch_bounds__(256) void mma_gemm_qkv(
    const __half* __restrict__ Ah, QkvPtrs p)
{
    int z = blockIdx.z;
    GSrc s{Ah, p.Bh[z]};
    mma_core(s, s, 32, p.bias[z], p.C[z], blockIdx.y * 128, blockIdx.x * 128);
}

__global__ __launch_bounds__(256) void mma_gemm_dual(
    const __half* A0h, const __half* B0h,
    const __half* A1h, const __half* B1h,
    const float* bias, float* C)
{
    GSrc s0{A0h, B0h};
    GSrc s1{A1h, B1h};
    mma_core(s0, s1, 64, bias, C, blockIdx.y * 128, blockIdx.x * 128);
}

// fold on tensor cores: z=0 -> W1 = sa_o@fuse_top, z=1 -> W2 = ta_o@fuse_bot
// K = 1024 -> nchunk = 32 (FIXED: was 8, summing only 256 of 1024 K-terms)
__global__ __launch_bounds__(256) void mma_gemm_fold(
    const __half* A0, const __half* B0,
    const __half* A1, const __half* B1,
    const float* zero, float* W1, float* W2)
{
    GSrc s = (blockIdx.z == 0) ? GSrc{A0, B0} : GSrc{A1, B1};
    float* C = (blockIdx.z == 0) ? W1 : W2;
    mma_core(s, s, 32, zero, C, blockIdx.y * 128, blockIdx.x * 128);
}

// ---------------------------------------------------------------------------
// fp32 -> fp16 convert, vectorized
// ---------------------------------------------------------------------------
__global__ __launch_bounds__(256) void cvt_half(
    const float4* __restrict__ X, __half* __restrict__ H)
{
    size_t idx = (size_t)blockIdx.x * 256 + threadIdx.x;
    float4 v = X[idx];
    __half h[4];
    h[0] = __float2half(v.x);
    h[1] = __float2half(v.y);
    h[2] = __float2half(v.z);
    h[3] = __float2half(v.w);
    *(uint2*)(H + idx * 4) = *(uint2*)h;
}

// ---------------------------------------------------------------------------
// Weight transpose + fp16 convert (z-batched): W[K,N] fp32 -> Th [N,K] fp16
// ---------------------------------------------------------------------------
struct WtPtrs {
    const float* W[6];
    __half* Th[6];
    int n;
};

__device__ __forceinline__ void wt_cvt_body(
    const float* __restrict__ W, __half* __restrict__ Th)
{
    __shared__ float t[32][33];
    int tx = threadIdx.x, ty = threadIdx.y;
    int n0 = blockIdx.x * 32, k0 = blockIdx.y * 32;
#pragma unroll
    for (int j = 0; j < 4; ++j) {
        int k = k0 + ty + j * 8;
        t[ty + j * 8][tx] = W[(size_t)k * DD + n0 + tx];
    }
    __syncthreads();
#pragma unroll
    for (int j = 0; j < 4; ++j) {
        int n = n0 + ty + j * 8;
        int k = k0 + tx;
        Th[(size_t)n * DD + k] = __float2half(t[tx][ty + j * 8]);
    }
}

__global__ void wt_cvt_batch(WtPtrs p)
{
    wt_cvt_body(p.W[blockIdx.z], p.Th[blockIdx.z]);
}

// ---------------------------------------------------------------------------
// Merged attention: blocks [0,2048) temporal, [2048,4096) spatial.
// fp32 q/k/v in, fp16 out. (R9-verified)
// ---------------------------------------------------------------------------
__device__ __forceinline__ void temporal_body(
    const float* __restrict__ Q, const float* __restrict__ Kp,
    const float* __restrict__ Vp, const int* __restrict__ mask,
    __half* __restrict__ O, int gid)
{
    __shared__ float Ks[64][64];
    __shared__ float Vs[64][64];
    __shared__ int Msk[64];

    int h = gid & 15;
    int clip = (gid >> 4) & 7;
    int b = gid >> 7;
    const size_t base = ((size_t)b * SS + clip) * DD + h * DK;
    const int RS = CLIPC * DD;

    int cq = threadIdx.x;
    unsigned long long qv[32];
    {
        const unsigned long long* qp =
            (const unsigned long long*)(Q + base + (size_t)cq * RS);
#pragma unroll
        for (int i = 0; i < 32; ++i) qv[i] = qp[i];
    }
    unsigned long long acc[32];
#pragma unroll
    for (int i = 0; i < 32; ++i) acc[i] = 0ull;
    float mmax = -1e30f, l = 0.f;

    const int lr = threadIdx.x >> 2;
    const int lc = (threadIdx.x & 3) << 4;

    for (int kt = 0; kt < 4; ++kt) {
        __syncthreads();
        {
            const float* krow = Kp + base + (size_t)(kt * 64 + lr) * RS;
            const float* vrow = Vp + base + (size_t)(kt * 64 + lr) * RS;
#pragma unroll
            for (int j = 0; j < 4; ++j) {
                *(float4*)&Ks[lr][lc + 4 * j] = *(const float4*)(krow + lc + 4 * j);
                *(float4*)&Vs[lr][lc + 4 * j] = *(const float4*)(vrow + lc + 4 * j);
            }
            if (threadIdx.x < 64)
                Msk[threadIdx.x] =
                    mask[(size_t)b * SS + (size_t)(kt * 64 + threadIdx.x) * CLIPC + clip];
        }
        __syncthreads();

        for (int kk = 0; kk < 64; ++kk) {
            if (Msk[kk] == 0) continue;
            const unsigned long long* kr = (const unsigned long long*)&Ks[kk][0];
            unsigned long long d2 = 0ull;
#pragma unroll
            for (int i = 0; i < 32; ++i) fma2(d2, qv[i], kr[i]);
            float2 dd = upk(d2);
            float s = (dd.x + dd.y) * 0.125f;
            if (s > mmax) {
                float corr = __expf(mmax - s);
                unsigned long long cc = pk2(corr, corr);
#pragma unroll
                for (int i = 0; i < 32; ++i) mul2(acc[i], cc);
                l *= corr;
                mmax = s;
            }
            float p = __expf(s - mmax);
            l += p;
            unsigned long long pp = pk2(p, p);
            const unsigned long long* vr = (const unsigned long long*)&Vs[kk][0];
#pragma unroll
            for (int i = 0; i < 32; ++i) fma2(acc[i], pp, vr[i]);
        }
    }
    float inv = 1.0f / l;
    __half2* op = (__half2*)(O + base + (size_t)cq * RS);
#pragma unroll
    for (int i = 0; i < 32; ++i) {
        float2 f = upk(acc[i]);
        op[i] = __floats2half2_rn(f.x * inv, f.y * inv);
    }
}

__device__ __forceinline__ void spatial_body(
    const float* __restrict__ Q, const float* __restrict__ Kp,
    const float* __restrict__ Vp, const int* __restrict__ mask,
    __half* __restrict__ O, int blk)
{
    int unit = blk * 2 + (threadIdx.x >> 7);
    int t = threadIdx.x & 127;
    int h = t >> 3, qi = t & 7;
    int b = unit >> 8, nc = unit & 255;
    size_t rowBase = (size_t)b * SS + (size_t)nc * CLIPC;

    unsigned long long qv[32];
    {
        const unsigned long long* qp =
            (const unsigned long long*)(Q + (rowBase + qi) * DD + h * DK);
#pragma unroll
        for (int i = 0; i < 32; ++i) qv[i] = qp[i];
    }
    const float* kbase = Kp + rowBase * DD + h * DK;
    float sc[8];
    float mx = -1e30f;
#pragma unroll
    for (int kk = 0; kk < 8; ++kk) {
        const unsigned long long* kr =
            (const unsigned long long*)(kbase + (size_t)kk * DD);
        unsigned long long d2 = 0ull;
#pragma unroll
        for (int i = 0; i < 32; ++i) fma2(d2, qv[i], kr[i]);
        float2 dd = upk(d2);
        float s = (dd.x + dd.y) * 0.125f;
        sc[kk] = (mask[rowBase + kk] != 0) ? s : -1e30f;
        mx = fmaxf(mx, sc[kk]);
    }
    float p[8], sum = 0.f;
#pragma unroll
    for (int kk = 0; kk < 8; ++kk) {
        p[kk] = __expf(sc[kk] - mx);
        sum += p[kk];
    }
    float inv = 1.0f / sum;
    unsigned long long acc[32];
#pragma unroll
    for (int i = 0; i < 32; ++i) acc[i] = 0ull;
    const float* vbase = Vp + rowBase * DD + h * DK;
#pragma unroll
    for (int kk = 0; kk < 8; ++kk) {
        unsigned long long pp = pk2(p[kk], p[kk]);
        const unsigned long long* vr =
            (const unsigned long long*)(vbase + (size_t)kk * DD);
#pragma unroll
        for (int i = 0; i < 32; ++i) fma2(acc[i], pp, vr[i]);
    }
    __half2* op = (__half2*)(O + (rowBase + qi) * DD + h * DK);
#pragma unroll
    for (int i = 0; i < 32; ++i) {
        float2 f = upk(acc[i]);
        op[i] = __floats2half2_rn(f.x * inv, f.y * inv);
    }
}

__global__ __launch_bounds__(256) void attn_merged(
    const float* __restrict__ qs, const float* __restrict__ ks,
    const float* __restrict__ vs, const float* __restrict__ qt,
    const float* __restrict__ kt, const float* __restrict__ vt,
    const int* __restrict__ mask, __half* __restrict__ csh,
    __half* __restrict__ cth)
{
    int blk = blockIdx.x;
    if (blk < BB * CLIPC * HH) {
        temporal_body(qt, kt, vt, mask, cth, blk);  // long blocks first
    } else {
        spatial_body(qs, ks, vs, mask, csh, blk - BB * CLIPC * HH);
    }
}

// ---------------------------------------------------------------------------
// bias combine, parallel 2-stage (exact fp32, unchanged)
// ---------------------------------------------------------------------------
__global__ void bias_partial(const float* __restrict__ sab,
                             const float* __restrict__ tab,
                             const float* __restrict__ fw,
                             float* __restrict__ part)
{
    int n = blockIdx.x * 256 + threadIdx.x;
    int j = blockIdx.y;
    int k0 = j * 64;
    float s = 0.f;
#pragma unroll 8
    for (int k = k0; k < k0 + 64; ++k) {
        float coef = (k < DD) ? sab[k] : tab[k - DD];
        s += coef * fw[(size_t)k * DD + n];
    }
    part[(size_t)j * DD + n] = s;
}

__global__ void bias_reduce(const float* __restrict__ part,
                            const float* __restrict__ fb,
                            float* __restrict__ bc)
{
    int n = blockIdx.x * 256 + threadIdx.x;
    float s = fb[n];
#pragma unroll
    for (int j = 0; j < 32; ++j) s += part[(size_t)j * DD + n];
    bc[n] = s;
}

// ---------------------------------------------------------------------------
// Launch sequence
// ---------------------------------------------------------------------------
extern "C" void kernel_launch(void* const* d_in, const int* in_sizes, int n_in,
                              void* d_out, int out_size)
{
    const float* x       = (const float*)d_in[0];
    const int*   mask    = (const int*)d_in[1];
    const float* sa_q_w  = (const float*)d_in[2];
    const float* sa_q_b  = (const float*)d_in[3];
    const float* sa_k_w  = (const float*)d_in[4];
    const float* sa_k_b  = (const float*)d_in[5];
    const float* sa_v_w  = (const float*)d_in[6];
    const float* sa_v_b  = (const float*)d_in[7];
    const float* sa_o_w  = (const float*)d_in[8];
    const float* sa_o_b  = (const float*)d_in[9];
    const float* ta_q_w  = (const float*)d_in[10];
    const float* ta_q_b  = (const float*)d_in[11];
    const float* ta_k_w  = (const float*)d_in[12];
    const float* ta_k_b  = (const float*)d_in[13];
    const float* ta_v_w  = (const float*)d_in[14];
    const float* ta_v_b  = (const float*)d_in[15];
    const float* ta_o_w  = (const float*)d_in[16];
    const float* ta_o_b  = (const float*)d_in[17];
    const float* fuse_w  = (const float*)d_in[18];
    const float* fuse_b  = (const float*)d_in[19];
    float* out = (float*)d_out;

    float *qs, *ks, *vs, *qt, *kt, *vt, *W1, *W2, *bc, *bcp, *zer;
    cudaGetSymbolAddress((void**)&qs, g_qs);
    cudaGetSymbolAddress((void**)&ks, g_ks);
    cudaGetSymbolAddress((void**)&vs, g_vs);
    cudaGetSymbolAddress((void**)&qt, g_qt);
    cudaGetSymbolAddress((void**)&kt, g_kt);
    cudaGetSymbolAddress((void**)&vt, g_vt);
    cudaGetSymbolAddress((void**)&W1, g_W1);
    cudaGetSymbolAddress((void**)&W2, g_W2);
    cudaGetSymbolAddress((void**)&bc, g_bc);
    cudaGetSymbolAddress((void**)&bcp, g_bcp);
    cudaGetSymbolAddress((void**)&zer, g_zero);

    __half *xh, *csh, *cth, *wth, *oh, *fth;
    cudaGetSymbolAddress((void**)&xh, g_xh);
    cudaGetSymbolAddress((void**)&csh, g_csh);
    cudaGetSymbolAddress((void**)&cth, g_cth);
    cudaGetSymbolAddress((void**)&wth, g_wth);
    cudaGetSymbolAddress((void**)&oh, g_oh);
    cudaGetSymbolAddress((void**)&fth, g_fth);
    const size_t WSZ = (size_t)DD * DD;

    cudaFuncSetAttribute(mma_gemm_qkv, cudaFuncAttributeMaxDynamicSharedMemorySize,
                         SMEM_DYN);
    cudaFuncSetAttribute(mma_gemm_dual, cudaFuncAttributeMaxDynamicSharedMemorySize,
                         SMEM_DYN);
    cudaFuncSetAttribute(mma_gemm_fold, cudaFuncAttributeMaxDynamicSharedMemorySize,
                         SMEM_DYN);

    const int nBlkCvt = MROWS * DD / 4 / 256;  // 32768
    const int nBlkCvtW = DD * DD / 4 / 256;    // 1024
    dim3 bT(32, 8);

    // 0) convert x to fp16
    cvt_half<<<nBlkCvt, 256>>>((const float4*)x, xh);

    // 1) transpose + convert the six QKV weights (z-batched)
    {
        WtPtrs wp;
        const float* ws[6] = {sa_q_w, sa_k_w, sa_v_w, ta_q_w, ta_k_w, ta_v_w};
        for (int i = 0; i < 6; ++i) {
            wp.W[i] = ws[i];
            wp.Th[i] = wth + i * WSZ;
        }
        wp.n = 6;
        wt_cvt_batch<<<dim3(32, 32, 6), bT>>>(wp);
    }

    // 2) fold prep: fp16 of o-weights (A) and transposed fuse halves (B)
    cvt_half<<<nBlkCvtW, 256>>>((const float4*)sa_o_w, oh + 0 * WSZ);
    cvt_half<<<nBlkCvtW, 256>>>((const float4*)ta_o_w, oh + 1 * WSZ);
    {
        WtPtrs wp;
        wp.W[0] = fuse_w;       wp.Th[0] = fth + 0 * WSZ;
        wp.W[1] = fuse_w + WSZ; wp.Th[1] = fth + 1 * WSZ;
        wp.n = 2;
        wt_cvt_batch<<<dim3(32, 32, 2), bT>>>(wp);
    }

    // 3) fold on tensor cores (z=2): W1 = sa_o@fuse_top, W2 = ta_o@fuse_bot
    mma_gemm_fold<<<dim3(8, 8, 2), 256, SMEM_DYN>>>(
        oh + 0 * WSZ, fth + 0 * WSZ, oh + 1 * WSZ, fth + 1 * WSZ, zer, W1, W2);

    // 4,5) combined bias (exact fp32)
    bias_partial<<<dim3(4, 32), 256>>>(sa_o_b, ta_o_b, fuse_w, bcp);
    bias_reduce<<<4, 256>>>(bcp, fuse_b, bc);

    // 6) six QKV projections on tensor cores (1-pass fp16)
    QkvPtrs qp;
    float* outs[6] = {qs, ks, vs, qt, kt, vt};
    const float* biases[6] = {sa_q_b, sa_k_b, sa_v_b, ta_q_b, ta_k_b, ta_v_b};
    for (int i = 0; i < 6; ++i) {
        qp.Bh[i] = wth + i * WSZ;
        qp.bias[i] = biases[i];
        qp.C[i] = outs[i];
    }
    mma_gemm_qkv<<<dim3(DD / 128, MROWS / 128, 6), 256, SMEM_DYN>>>(xh, qp);

    // 7) transpose + convert folded W1/W2 (z-batched)
    {
        WtPtrs wp;
        wp.W[0] = W1; wp.Th[0] = wth + 6 * WSZ;
        wp.W[1] = W2; wp.Th[1] = wth + 7 * WSZ;
        wp.n = 2;
        wt_cvt_batch<<<dim3(32, 32, 2), bT>>>(wp);
    }

    // 8) merged attention (temporal first, spatial backfills)
    attn_merged<<<BB * CLIPC * HH + BB * NCC / 2, 256>>>(
        qs, ks, vs, qt, kt, vt, mask, csh, cth);

    // 9) fused output: out = cs@W1t + ct@W2t + bc (single dual-K tensor GEMM)
    mma_gemm_dual<<<dim3(DD / 128, MROWS / 128), 256, SMEM_DYN>>>(
        csh, wth + 6 * WSZ, cth, wth + 7 * WSZ, bc, out);
}